// round 6
// baseline (speedup 1.0000x reference)
#include <cuda_runtime.h>
#include <cstdint>

#define T_STEPS 12
#define IN_DIM  64
#define HID_DIM 128
#define EMB     64
#define G3      192

#define NMAX    10240
#define EDGEMAX 360448   /* > E + N */

// ---------------- scratch (static __device__, no allocations) ----------------
__device__ float g_deg [NMAX];
__device__ float g_dinv[NMAX];
__device__ int   g_cnt [NMAX];
__device__ int   g_off [NMAX + 1];
__device__ int   g_cur [NMAX];
__device__ int2  g_ce  [EDGEMAX];                       // (row, norm-as-int)
__device__ float g_xagg[(size_t)T_STEPS * NMAX * IN_DIM];
__device__ float g_H   [(size_t)T_STEPS * NMAX * HID_DIM];
__device__ float g_M2  [(size_t)T_STEPS * NMAX * EMB];
__device__ float g_zseq[(size_t)T_STEPS * NMAX * EMB];
__device__ float g_gi  [(size_t)T_STEPS * NMAX * G3];
__device__ float g_h   [(size_t)NMAX * EMB];
__device__ float g_WTih[EMB * G3];
__device__ float g_WThh[EMB * G3];

// ---------------- small helpers ----------------
__device__ __forceinline__ float sigf(float x) { return 1.f / (1.f + __expf(-x)); }

__device__ __forceinline__ float softplusf(float x) {
    float u = __expf(-fabsf(x));                 // = exp(x) when x<0
    float r = fmaxf(x, 0.f) + __logf(1.f + u);
    if (x < -15.f) r = u;                        // avoid 1+u==1 rounding
    return r;
}

__device__ __forceinline__ unsigned long long dup2(float a) {
    unsigned long long r;
    asm("mov.b64 %0, {%1, %1};" : "=l"(r) : "f"(a));
    return r;
}
__device__ __forceinline__ void fma2(unsigned long long& d, unsigned long long a, unsigned long long b) {
    asm("fma.rn.f32x2 %0, %1, %2, %0;" : "+l"(d) : "l"(a), "l"(b));
}

// ---------------- graph preprocessing ----------------
__global__ void k_init(int n) {
    int i = blockIdx.x * blockDim.x + threadIdx.x;
    if (i < n) { g_deg[i] = 1.f; g_cnt[i] = 1; }   // self-loop weight/count
}

// edge_index is INT32 (JAX without x64 demotes int64 -> int32): layout [2, E]
__global__ void k_degcnt(const int* __restrict__ ei, const float* __restrict__ ew, int E, int n) {
    int e = blockIdx.x * blockDim.x + threadIdx.x;
    if (e < E) {
        int c = ei[E + e];
        c = min(max(c, 0), n - 1);               // defensive clamp
        atomicAdd(&g_deg[c], ew[e]);
        atomicAdd(&g_cnt[c], 1);
    }
}

__global__ void k_dinv(int n) {
    int i = blockIdx.x * blockDim.x + threadIdx.x;
    if (i < n) {
        float d = g_deg[i];
        g_dinv[i] = (d > 0.f) ? rsqrtf(d) : 0.f;
    }
}

__global__ void k_scan(int n) {      // <<<1, 1024>>>
    __shared__ int sums[1024];
    int tid = threadIdx.x;
    int per = (n + 1023) / 1024;
    int start = tid * per;
    int end   = min(start + per, n);
    int s = 0;
    for (int i = start; i < end; i++) s += g_cnt[i];
    sums[tid] = s;
    __syncthreads();
    for (int d = 1; d < 1024; d <<= 1) {
        int v = 0;
        if (tid >= d) v = sums[tid - d];
        __syncthreads();
        if (tid >= d) sums[tid] += v;
        __syncthreads();
    }
    int base = (tid == 0) ? 0 : sums[tid - 1];
    for (int i = start; i < end; i++) {
        g_off[i] = base; g_cur[i] = base;
        base += g_cnt[i];
    }
    if (tid == 1023) g_off[n] = sums[1023];
}

__global__ void k_fill(const int* __restrict__ ei, const float* __restrict__ ew, int E, int n) {
    int e = blockIdx.x * blockDim.x + threadIdx.x;
    int total = E + n;
    if (e >= total) return;
    int r, c; float w;
    if (e < E) {
        r = ei[e]; c = ei[E + e]; w = ew[e];
        r = min(max(r, 0), n - 1);
        c = min(max(c, 0), n - 1);
    }
    else       { r = c = e - E; w = 1.f; }
    float norm = g_dinv[r] * w * g_dinv[c];
    int pos = atomicAdd(&g_cur[c], 1);
    pos = min(max(pos, 0), EDGEMAX - 1);         // defensive clamp
    g_ce[pos] = make_int2(r, __float_as_int(norm));
}

// ---------------- aggregation (64-wide features), warp per (node, t) ----------------
__global__ void k_agg(const float* __restrict__ in, float* __restrict__ out,
                      const float* __restrict__ bias, int n) {
    int w    = (blockIdx.x * blockDim.x + threadIdx.x) >> 5;
    int lane = threadIdx.x & 31;
    if (w >= n * T_STEPS) return;
    int t = w / n, nd = w - t * n;
    int s = g_off[nd], e = g_off[nd + 1];
    const float* base = in + (size_t)t * n * 64;
    float a0 = 0.f, a1 = 0.f;
    int j = s;
    for (; j + 1 < e; j += 2) {
        int2 p0 = g_ce[j], p1 = g_ce[j + 1];
        float2 v0 = *(const float2*)(base + (size_t)p0.x * 64 + lane * 2);
        float2 v1 = *(const float2*)(base + (size_t)p1.x * 64 + lane * 2);
        float w0 = __int_as_float(p0.y), w1 = __int_as_float(p1.y);
        a0 = fmaf(w0, v0.x, a0); a1 = fmaf(w0, v0.y, a1);
        a0 = fmaf(w1, v1.x, a0); a1 = fmaf(w1, v1.y, a1);
    }
    if (j < e) {
        int2 p0 = g_ce[j];
        float2 v0 = *(const float2*)(base + (size_t)p0.x * 64 + lane * 2);
        float w0 = __int_as_float(p0.y);
        a0 = fmaf(w0, v0.x, a0); a1 = fmaf(w0, v0.y, a1);
    }
    if (bias) { a0 += bias[lane * 2]; a1 += bias[lane * 2 + 1]; }
    float2* o = (float2*)(out + ((size_t)t * n + nd) * 64);
    o[lane] = make_float2(a0, a1);
}

// ---------------- generic tiled GEMM: C[M,NC] = act(A[M,K] @ B[K,NC] + bias) ----------------
__global__ void __launch_bounds__(256) k_gemm(const float* __restrict__ A, const float* __restrict__ B,
                                              const float* __restrict__ bias, float* __restrict__ C,
                                              int M, int K, int NC, int relu) {
    __shared__ float As[16][68];
    __shared__ float Bs[16][68];
    int r0 = blockIdx.x * 64, c0 = blockIdx.y * 64;
    int tid = threadIdx.x;
    int ty = tid >> 4, tx = tid & 15;
    float acc[4][4] = {};
    for (int k0 = 0; k0 < K; k0 += 16) {
        {   // A tile -> transposed
            int m = tid >> 2, kb = (tid & 3) << 2;
            float4 v = make_float4(0.f, 0.f, 0.f, 0.f);
            if (r0 + m < M) v = *(const float4*)(A + (size_t)(r0 + m) * K + k0 + kb);
            As[kb + 0][m] = v.x; As[kb + 1][m] = v.y; As[kb + 2][m] = v.z; As[kb + 3][m] = v.w;
        }
        {   // B tile
            int k = tid >> 4, nb = (tid & 15) << 2;
            *(float4*)&Bs[k][nb] = *(const float4*)(B + (size_t)(k0 + k) * NC + c0 + nb);
        }
        __syncthreads();
        #pragma unroll
        for (int k = 0; k < 16; k++) {
            float4 a = *(const float4*)&As[k][ty << 2];
            float4 b = *(const float4*)&Bs[k][tx << 2];
            float ar[4] = {a.x, a.y, a.z, a.w};
            float br[4] = {b.x, b.y, b.z, b.w};
            #pragma unroll
            for (int i = 0; i < 4; i++)
                #pragma unroll
                for (int jj = 0; jj < 4; jj++)
                    acc[i][jj] = fmaf(ar[i], br[jj], acc[i][jj]);
        }
        __syncthreads();
    }
    #pragma unroll
    for (int i = 0; i < 4; i++) {
        int row = r0 + (ty << 2) + i;
        if (row >= M) continue;
        #pragma unroll
        for (int jj = 0; jj < 4; jj++) {
            int col = c0 + (tx << 2) + jj;
            float v = acc[i][jj];
            if (bias) v += bias[col];
            if (relu) v = fmaxf(v, 0.f);
            C[(size_t)row * NC + col] = v;
        }
    }
}

// ---------------- weight transpose [192,64] -> [64,192] ----------------
__global__ void k_transpose(const float* __restrict__ in, float* __restrict__ out) {
    int i = blockIdx.x * blockDim.x + threadIdx.x;
    if (i < EMB * G3) {
        int k = i / G3, g = i - k * G3;
        out[i] = in[g * EMB + k];
    }
}

__global__ void k_zero(float* p, int n) {
    int i = blockIdx.x * blockDim.x + threadIdx.x;
    if (i < n) p[i] = 0.f;
}

// ---------------- fused GRU step: gh GEMM (64x192 tile) + gate update in-place ----------------
__global__ void __launch_bounds__(256) k_gru(const float* __restrict__ bhh, int n, int t) {
    __shared__ float S[12288];                   // 48 KB
    float* As = S;                               // [16][68]
    float* Bs = S + 1088;                        // [16][196]
    float* Cs = S;                               // [64][192] (reused)
    int r0 = blockIdx.x * 64;
    int tid = threadIdx.x;
    int ty = tid >> 4, tx = tid & 15;
    float acc[4][12] = {};
    for (int k0 = 0; k0 < 64; k0 += 16) {
        {
            int m = tid >> 2, kb = (tid & 3) << 2;
            float4 v = make_float4(0.f, 0.f, 0.f, 0.f);
            if (r0 + m < n) v = *(const float4*)(g_h + (size_t)(r0 + m) * 64 + k0 + kb);
            As[(kb + 0) * 68 + m] = v.x; As[(kb + 1) * 68 + m] = v.y;
            As[(kb + 2) * 68 + m] = v.z; As[(kb + 3) * 68 + m] = v.w;
        }
        {
            int k = tid >> 4, nb = (tid & 15) * 12;
            const float* bp = g_WThh + (size_t)(k0 + k) * 192 + nb;
            *(float4*)&Bs[k * 196 + nb + 0] = *(const float4*)(bp + 0);
            *(float4*)&Bs[k * 196 + nb + 4] = *(const float4*)(bp + 4);
            *(float4*)&Bs[k * 196 + nb + 8] = *(const float4*)(bp + 8);
        }
        __syncthreads();
        #pragma unroll
        for (int k = 0; k < 16; k++) {
            float4 a = *(const float4*)&As[k * 68 + (ty << 2)];
            float ar[4] = {a.x, a.y, a.z, a.w};
            float br[12];
            float4 b0 = *(const float4*)&Bs[k * 196 + tx * 12 + 0];
            float4 b1 = *(const float4*)&Bs[k * 196 + tx * 12 + 4];
            float4 b2 = *(const float4*)&Bs[k * 196 + tx * 12 + 8];
            br[0]=b0.x;br[1]=b0.y;br[2]=b0.z;br[3]=b0.w;
            br[4]=b1.x;br[5]=b1.y;br[6]=b1.z;br[7]=b1.w;
            br[8]=b2.x;br[9]=b2.y;br[10]=b2.z;br[11]=b2.w;
            #pragma unroll
            for (int i = 0; i < 4; i++)
                #pragma unroll
                for (int jj = 0; jj < 12; jj++)
                    acc[i][jj] = fmaf(ar[i], br[jj], acc[i][jj]);
        }
        __syncthreads();
    }
    // stash gh tile to smem (reuse)
    #pragma unroll
    for (int i = 0; i < 4; i++)
        #pragma unroll
        for (int jj = 0; jj < 12; jj++)
            Cs[((ty << 2) + i) * 192 + tx * 12 + jj] = acc[i][jj];
    __syncthreads();
    // gates: 64 rows * 64 feats = 4096 elems, 16 per thread
    #pragma unroll
    for (int rep = 0; rep < 16; rep++) {
        int e = tid + rep * 256;
        int row = e >> 6, f = e & 63;
        int grow = r0 + row;
        if (grow < n) {
            float hr = Cs[row * 192 + f       ] + bhh[f       ];
            float hz = Cs[row * 192 + 64 + f  ] + bhh[64 + f  ];
            float hn = Cs[row * 192 + 128 + f ] + bhh[128 + f ];
            const float* gi = g_gi + ((size_t)t * n + grow) * 192;
            float r  = sigf(gi[f] + hr);
            float zg = sigf(gi[64 + f] + hz);
            float ng = tanhf(gi[128 + f] + r * hn);
            float ho = g_h[(size_t)grow * 64 + f];
            g_h[(size_t)grow * 64 + f] = (1.f - zg) * ng + zg * ho;
        }
    }
}

// ---------------- decoder: softplus(z @ z^T + b), packed f32x2 FMA ----------------
__global__ void __launch_bounds__(256) k_decode(float* __restrict__ C, const float* __restrict__ dbias, int n) {
    __shared__ float As[32 * 128];
    __shared__ float Bs[32 * 128];
    int i0 = blockIdx.y * 128, j0 = blockIdx.x * 128;
    int tid = threadIdx.x;
    int ty = tid >> 4, tx = tid & 15;
    unsigned long long acc[8][4];
    #pragma unroll
    for (int i = 0; i < 8; i++)
        #pragma unroll
        for (int jj = 0; jj < 4; jj++) acc[i][jj] = 0ULL;

    for (int k0 = 0; k0 < 64; k0 += 32) {
        {   // load A (z rows i0..i0+127, k chunk) transposed
            int row = tid >> 1, kb = (tid & 1) * 16;
            #pragma unroll
            for (int c = 0; c < 4; c++) {
                float4 v = make_float4(0.f, 0.f, 0.f, 0.f);
                if (i0 + row < n) v = *(const float4*)(g_h + (size_t)(i0 + row) * 64 + k0 + kb + c * 4);
                As[(kb + c * 4 + 0) * 128 + row] = v.x;
                As[(kb + c * 4 + 1) * 128 + row] = v.y;
                As[(kb + c * 4 + 2) * 128 + row] = v.z;
                As[(kb + c * 4 + 3) * 128 + row] = v.w;
            }
        }
        {   // load B (z rows j0..)
            int row = tid >> 1, kb = (tid & 1) * 16;
            #pragma unroll
            for (int c = 0; c < 4; c++) {
                float4 v = make_float4(0.f, 0.f, 0.f, 0.f);
                if (j0 + row < n) v = *(const float4*)(g_h + (size_t)(j0 + row) * 64 + k0 + kb + c * 4);
                Bs[(kb + c * 4 + 0) * 128 + row] = v.x;
                Bs[(kb + c * 4 + 1) * 128 + row] = v.y;
                Bs[(kb + c * 4 + 2) * 128 + row] = v.z;
                Bs[(kb + c * 4 + 3) * 128 + row] = v.w;
            }
        }
        __syncthreads();
        #pragma unroll
        for (int k = 0; k < 32; k++) {
            const float* ap = &As[k * 128 + (ty << 3)];
            float4 a0 = *(const float4*)ap;
            float4 a1 = *(const float4*)(ap + 4);
            unsigned long long ad[8] = { dup2(a0.x), dup2(a0.y), dup2(a0.z), dup2(a0.w),
                                         dup2(a1.x), dup2(a1.y), dup2(a1.z), dup2(a1.w) };
            const unsigned long long* bp = (const unsigned long long*)&Bs[k * 128 + (tx << 3)];
            unsigned long long b0 = bp[0], b1 = bp[1], b2 = bp[2], b3 = bp[3];
            #pragma unroll
            for (int i = 0; i < 8; i++) {
                fma2(acc[i][0], ad[i], b0);
                fma2(acc[i][1], ad[i], b1);
                fma2(acc[i][2], ad[i], b2);
                fma2(acc[i][3], ad[i], b3);
            }
        }
        __syncthreads();
    }
    float db = dbias[0];
    #pragma unroll
    for (int i = 0; i < 8; i++) {
        int gi_ = i0 + (ty << 3) + i;
        if (gi_ >= n) continue;
        float vals[8];
        #pragma unroll
        for (int jj = 0; jj < 4; jj++) {
            float lo, hi;
            asm("mov.b64 {%0, %1}, %2;" : "=f"(lo), "=f"(hi) : "l"(acc[i][jj]));
            vals[2 * jj + 0] = softplusf(lo + db);
            vals[2 * jj + 1] = softplusf(hi + db);
        }
        int gj = j0 + (tx << 3);
        float* cp = C + (size_t)gi_ * n + gj;
        if (gj + 8 <= n) {
            *(float4*)cp       = make_float4(vals[0], vals[1], vals[2], vals[3]);
            *(float4*)(cp + 4) = make_float4(vals[4], vals[5], vals[6], vals[7]);
        } else {
            for (int jj = 0; jj < 8; jj++)
                if (gj + jj < n) cp[jj] = vals[jj];
        }
    }
}

__global__ void k_copyz(float* __restrict__ out, int n) {
    int i = blockIdx.x * blockDim.x + threadIdx.x;
    if (i < n * 64) out[(size_t)n * n + i] = g_h[i];
}

// ---------------- host ----------------
extern "C" void kernel_launch(void* const* d_in, const int* in_sizes, int n_in,
                              void* d_out, int out_size) {
    const float* x     = (const float*)d_in[0];
    const int*   ei    = (const int*)d_in[1];      // int32! (JAX demotes int64)
    const float* ew    = (const float*)d_in[2];
    const float* W1    = (const float*)d_in[3];
    const float* b1    = (const float*)d_in[4];
    const float* W2    = (const float*)d_in[5];
    const float* b2    = (const float*)d_in[6];
    const float* Wih   = (const float*)d_in[7];
    const float* Whh   = (const float*)d_in[8];
    const float* bih   = (const float*)d_in[9];
    const float* bhh   = (const float*)d_in[10];
    const float* dbias = (const float*)d_in[11];
    float* out = (float*)d_out;

    int E = in_sizes[2];
    int N = in_sizes[0] / (T_STEPS * IN_DIM);
    if (N > NMAX) N = NMAX;                        // hard guard: never OOB scratch
    if (E > EDGEMAX - N) E = EDGEMAX - N;
    int M = T_STEPS * N;

    float *p_xagg, *p_H, *p_M2, *p_zseq, *p_gi, *p_h, *p_WTih, *p_WThh;
    cudaGetSymbolAddress((void**)&p_xagg, g_xagg);
    cudaGetSymbolAddress((void**)&p_H,    g_H);
    cudaGetSymbolAddress((void**)&p_M2,   g_M2);
    cudaGetSymbolAddress((void**)&p_zseq, g_zseq);
    cudaGetSymbolAddress((void**)&p_gi,   g_gi);
    cudaGetSymbolAddress((void**)&p_h,    g_h);
    cudaGetSymbolAddress((void**)&p_WTih, g_WTih);
    cudaGetSymbolAddress((void**)&p_WThh, g_WThh);

    const int B = 256;
    // graph preprocessing
    k_init  <<<(N + B - 1) / B, B>>>(N);
    k_degcnt<<<(E + B - 1) / B, B>>>(ei, ew, E, N);
    k_dinv  <<<(N + B - 1) / B, B>>>(N);
    k_scan  <<<1, 1024>>>(N);
    k_fill  <<<(E + N + B - 1) / B, B>>>(ei, ew, E, N);

    // encoder: AX -> (AX)W1+b1,relu -> HW2 -> A(HW2)+b2
    int aggBlocks = (N * T_STEPS * 32 + B - 1) / B;
    k_agg <<<aggBlocks, B>>>(x, p_xagg, nullptr, N);
    k_gemm<<<dim3((M + 63) / 64, HID_DIM / 64), B>>>(p_xagg, W1, b1, p_H, M, IN_DIM, HID_DIM, 1);
    k_gemm<<<dim3((M + 63) / 64, EMB / 64),     B>>>(p_H, W2, nullptr, p_M2, M, HID_DIM, EMB, 0);
    k_agg <<<aggBlocks, B>>>(p_M2, p_zseq, b2, N);

    // GRU
    k_transpose<<<(EMB * G3 + B - 1) / B, B>>>(Wih, p_WTih);
    k_transpose<<<(EMB * G3 + B - 1) / B, B>>>(Whh, p_WThh);
    k_gemm<<<dim3((M + 63) / 64, G3 / 64), B>>>(p_zseq, p_WTih, bih, p_gi, M, EMB, G3, 0);
    k_zero<<<(N * EMB + B - 1) / B, B>>>(p_h, N * EMB);
    for (int t = 0; t < T_STEPS; t++)
        k_gru<<<(N + 63) / 64, B>>>(bhh, N, t);

    // decoder + z output
    int gb = (N + 127) / 128;
    k_decode<<<dim3(gb, gb), B>>>(out, dbias, N);
    k_copyz <<<(N * EMB + B - 1) / B, B>>>(out, N);
}

// round 7
// speedup vs baseline: 1.0990x; 1.0990x over previous
#include <cuda_runtime.h>
#include <cstdint>

#define T_STEPS 12
#define IN_DIM  64
#define HID_DIM 128
#define EMB     64
#define G3      192

#define NMAX    10240
#define EDGEMAX 360448   /* > E + N */

// ---------------- scratch (static __device__, no allocations) ----------------
__device__ float g_deg [NMAX];
__device__ float g_dinv[NMAX];
__device__ int   g_cnt [NMAX];
__device__ int   g_off [NMAX + 1];
__device__ int   g_cur [NMAX];
__device__ int2  g_ce  [EDGEMAX];                       // (row, norm-as-int)
__device__ float g_xagg[(size_t)T_STEPS * NMAX * IN_DIM];
__device__ float g_H   [(size_t)T_STEPS * NMAX * HID_DIM];
__device__ float g_M2  [(size_t)T_STEPS * NMAX * EMB];
__device__ float g_zseq[(size_t)T_STEPS * NMAX * EMB];
__device__ float g_gi  [(size_t)T_STEPS * NMAX * G3];
__device__ float g_h   [(size_t)NMAX * EMB];
__device__ float g_WTih[EMB * G3];
__device__ float g_WThh[EMB * G3];

// ---------------- small helpers ----------------
__device__ __forceinline__ float sigf(float x) { return 1.f / (1.f + __expf(-x)); }

__device__ __forceinline__ float softplusf(float x) {
    float u = __expf(-fabsf(x));                 // = exp(x) when x<0
    float r = fmaxf(x, 0.f) + __logf(1.f + u);
    if (x < -15.f) r = u;                        // avoid 1+u==1 rounding
    return r;
}

__device__ __forceinline__ unsigned long long dup2(float a) {
    unsigned long long r;
    asm("mov.b64 %0, {%1, %1};" : "=l"(r) : "f"(a));
    return r;
}
__device__ __forceinline__ unsigned long long pack2(float lo, float hi) {
    unsigned long long r;
    asm("mov.b64 %0, {%1, %2};" : "=l"(r) : "f"(lo), "f"(hi));
    return r;
}
__device__ __forceinline__ float2 unpack2(unsigned long long v) {
    float lo, hi;
    asm("mov.b64 {%0, %1}, %2;" : "=f"(lo), "=f"(hi) : "l"(v));
    return make_float2(lo, hi);
}
__device__ __forceinline__ void fma2(unsigned long long& d, unsigned long long a, unsigned long long b) {
    asm("fma.rn.f32x2 %0, %1, %2, %0;" : "+l"(d) : "l"(a), "l"(b));
}

// ---------------- graph preprocessing ----------------
__global__ void k_init(int n) {
    int i = blockIdx.x * blockDim.x + threadIdx.x;
    if (i < n) { g_deg[i] = 1.f; g_cnt[i] = 1; }   // self-loop weight/count
}

// edge_index is INT32 (JAX without x64 demotes int64 -> int32): layout [2, E]
__global__ void k_degcnt(const int* __restrict__ ei, const float* __restrict__ ew, int E, int n) {
    int e = blockIdx.x * blockDim.x + threadIdx.x;
    if (e < E) {
        int c = ei[E + e];
        c = min(max(c, 0), n - 1);               // defensive clamp
        atomicAdd(&g_deg[c], ew[e]);
        atomicAdd(&g_cnt[c], 1);
    }
}

__global__ void k_dinv(int n) {
    int i = blockIdx.x * blockDim.x + threadIdx.x;
    if (i < n) {
        float d = g_deg[i];
        g_dinv[i] = (d > 0.f) ? rsqrtf(d) : 0.f;
    }
}

__global__ void k_scan(int n) {      // <<<1, 1024>>>
    __shared__ int sums[1024];
    int tid = threadIdx.x;
    int per = (n + 1023) / 1024;
    int start = tid * per;
    int end   = min(start + per, n);
    int s = 0;
    for (int i = start; i < end; i++) s += g_cnt[i];
    sums[tid] = s;
    __syncthreads();
    for (int d = 1; d < 1024; d <<= 1) {
        int v = 0;
        if (tid >= d) v = sums[tid - d];
        __syncthreads();
        if (tid >= d) sums[tid] += v;
        __syncthreads();
    }
    int base = (tid == 0) ? 0 : sums[tid - 1];
    for (int i = start; i < end; i++) {
        g_off[i] = base; g_cur[i] = base;
        base += g_cnt[i];
    }
    if (tid == 1023) g_off[n] = sums[1023];
}

__global__ void k_fill(const int* __restrict__ ei, const float* __restrict__ ew, int E, int n) {
    int e = blockIdx.x * blockDim.x + threadIdx.x;
    int total = E + n;
    if (e >= total) return;
    int r, c; float w;
    if (e < E) {
        r = ei[e]; c = ei[E + e]; w = ew[e];
        r = min(max(r, 0), n - 1);
        c = min(max(c, 0), n - 1);
    }
    else       { r = c = e - E; w = 1.f; }
    float norm = g_dinv[r] * w * g_dinv[c];
    int pos = atomicAdd(&g_cur[c], 1);
    pos = min(max(pos, 0), EDGEMAX - 1);         // defensive clamp
    g_ce[pos] = make_int2(r, __float_as_int(norm));
}

// ---------------- aggregation (64-wide features), warp per (node, t) ----------------
__global__ void k_agg(const float* __restrict__ in, float* __restrict__ out,
                      const float* __restrict__ bias, int n) {
    int w    = (blockIdx.x * blockDim.x + threadIdx.x) >> 5;
    int lane = threadIdx.x & 31;
    if (w >= n * T_STEPS) return;
    int t = w / n, nd = w - t * n;
    int s = g_off[nd], e = g_off[nd + 1];
    const float* base = in + (size_t)t * n * 64;
    float a0 = 0.f, a1 = 0.f;
    int j = s;
    for (; j + 3 < e; j += 4) {                  // 4-way unroll for MLP
        int2 p0 = g_ce[j], p1 = g_ce[j + 1], p2 = g_ce[j + 2], p3 = g_ce[j + 3];
        float2 v0 = *(const float2*)(base + (size_t)p0.x * 64 + lane * 2);
        float2 v1 = *(const float2*)(base + (size_t)p1.x * 64 + lane * 2);
        float2 v2 = *(const float2*)(base + (size_t)p2.x * 64 + lane * 2);
        float2 v3 = *(const float2*)(base + (size_t)p3.x * 64 + lane * 2);
        float w0 = __int_as_float(p0.y), w1 = __int_as_float(p1.y);
        float w2 = __int_as_float(p2.y), w3 = __int_as_float(p3.y);
        a0 = fmaf(w0, v0.x, a0); a1 = fmaf(w0, v0.y, a1);
        a0 = fmaf(w1, v1.x, a0); a1 = fmaf(w1, v1.y, a1);
        a0 = fmaf(w2, v2.x, a0); a1 = fmaf(w2, v2.y, a1);
        a0 = fmaf(w3, v3.x, a0); a1 = fmaf(w3, v3.y, a1);
    }
    for (; j < e; j++) {
        int2 p0 = g_ce[j];
        float2 v0 = *(const float2*)(base + (size_t)p0.x * 64 + lane * 2);
        float w0 = __int_as_float(p0.y);
        a0 = fmaf(w0, v0.x, a0); a1 = fmaf(w0, v0.y, a1);
    }
    if (bias) { a0 += bias[lane * 2]; a1 += bias[lane * 2 + 1]; }
    float2* o = (float2*)(out + ((size_t)t * n + nd) * 64);
    o[lane] = make_float2(a0, a1);
}

// ---------------- generic tiled GEMM: C[M,NC] = act(A[M,K] @ B[K,NC] + bias) ----------------
__global__ void __launch_bounds__(256) k_gemm(const float* __restrict__ A, const float* __restrict__ B,
                                              const float* __restrict__ bias, float* __restrict__ C,
                                              int M, int K, int NC, int relu) {
    __shared__ float As[16][68];
    __shared__ float Bs[16][68];
    int r0 = blockIdx.x * 64, c0 = blockIdx.y * 64;
    int tid = threadIdx.x;
    int ty = tid >> 4, tx = tid & 15;
    unsigned long long acc[4][2];
    #pragma unroll
    for (int i = 0; i < 4; i++) { acc[i][0] = 0ULL; acc[i][1] = 0ULL; }
    for (int k0 = 0; k0 < K; k0 += 16) {
        {   // A tile -> transposed
            int m = tid >> 2, kb = (tid & 3) << 2;
            float4 v = make_float4(0.f, 0.f, 0.f, 0.f);
            if (r0 + m < M) v = *(const float4*)(A + (size_t)(r0 + m) * K + k0 + kb);
            As[kb + 0][m] = v.x; As[kb + 1][m] = v.y; As[kb + 2][m] = v.z; As[kb + 3][m] = v.w;
        }
        {   // B tile
            int k = tid >> 4, nb = (tid & 15) << 2;
            *(float4*)&Bs[k][nb] = *(const float4*)(B + (size_t)(k0 + k) * NC + c0 + nb);
        }
        __syncthreads();
        #pragma unroll
        for (int k = 0; k < 16; k++) {
            float4 a = *(const float4*)&As[k][ty << 2];
            unsigned long long ad[4] = { dup2(a.x), dup2(a.y), dup2(a.z), dup2(a.w) };
            const unsigned long long* bp = (const unsigned long long*)&Bs[k][tx << 2];
            unsigned long long b0 = bp[0], b1 = bp[1];
            #pragma unroll
            for (int i = 0; i < 4; i++) {
                fma2(acc[i][0], ad[i], b0);
                fma2(acc[i][1], ad[i], b1);
            }
        }
        __syncthreads();
    }
    #pragma unroll
    for (int i = 0; i < 4; i++) {
        int row = r0 + (ty << 2) + i;
        if (row >= M) continue;
        float2 p0 = unpack2(acc[i][0]);
        float2 p1 = unpack2(acc[i][1]);
        float vv[4] = { p0.x, p0.y, p1.x, p1.y };
        #pragma unroll
        for (int jj = 0; jj < 4; jj++) {
            int col = c0 + (tx << 2) + jj;
            float v = vv[jj];
            if (bias) v += bias[col];
            if (relu) v = fmaxf(v, 0.f);
            C[(size_t)row * NC + col] = v;
        }
    }
}

// ---------------- weight transpose [192,64] -> [64,192] ----------------
__global__ void k_transpose(const float* __restrict__ in, float* __restrict__ out) {
    int i = blockIdx.x * blockDim.x + threadIdx.x;
    if (i < EMB * G3) {
        int k = i / G3, g = i - k * G3;
        out[i] = in[g * EMB + k];
    }
}

__global__ void k_zero(float* p, int n) {
    int i = blockIdx.x * blockDim.x + threadIdx.x;
    if (i < n) p[i] = 0.f;
}

// ---------------- fused GRU step: gh GEMM (64x192 tile) + gate update in-place ----------------
__global__ void __launch_bounds__(256) k_gru(const float* __restrict__ bhh, int n, int t) {
    __shared__ float S[12288];                   // 48 KB
    float* As = S;                               // [16][68]
    float* Bs = S + 1088;                        // [16][196]
    float* Cs = S;                               // [64][192] (reused)
    int r0 = blockIdx.x * 64;
    int tid = threadIdx.x;
    int ty = tid >> 4, tx = tid & 15;
    unsigned long long acc[4][6];
    #pragma unroll
    for (int i = 0; i < 4; i++)
        #pragma unroll
        for (int jj = 0; jj < 6; jj++) acc[i][jj] = 0ULL;
    for (int k0 = 0; k0 < 64; k0 += 16) {
        {
            int m = tid >> 2, kb = (tid & 3) << 2;
            float4 v = make_float4(0.f, 0.f, 0.f, 0.f);
            if (r0 + m < n) v = *(const float4*)(g_h + (size_t)(r0 + m) * 64 + k0 + kb);
            As[(kb + 0) * 68 + m] = v.x; As[(kb + 1) * 68 + m] = v.y;
            As[(kb + 2) * 68 + m] = v.z; As[(kb + 3) * 68 + m] = v.w;
        }
        {
            int k = tid >> 4, nb = (tid & 15) * 12;
            const float* bp = g_WThh + (size_t)(k0 + k) * 192 + nb;
            *(float4*)&Bs[k * 196 + nb + 0] = *(const float4*)(bp + 0);
            *(float4*)&Bs[k * 196 + nb + 4] = *(const float4*)(bp + 4);
            *(float4*)&Bs[k * 196 + nb + 8] = *(const float4*)(bp + 8);
        }
        __syncthreads();
        #pragma unroll
        for (int k = 0; k < 16; k++) {
            float4 a = *(const float4*)&As[k * 68 + (ty << 2)];
            unsigned long long ad[4] = { dup2(a.x), dup2(a.y), dup2(a.z), dup2(a.w) };
            const unsigned long long* bp = (const unsigned long long*)&Bs[k * 196 + tx * 12];
            unsigned long long b0 = bp[0], b1 = bp[1], b2 = bp[2];
            unsigned long long b3 = bp[3], b4 = bp[4], b5 = bp[5];
            #pragma unroll
            for (int i = 0; i < 4; i++) {
                fma2(acc[i][0], ad[i], b0);
                fma2(acc[i][1], ad[i], b1);
                fma2(acc[i][2], ad[i], b2);
                fma2(acc[i][3], ad[i], b3);
                fma2(acc[i][4], ad[i], b4);
                fma2(acc[i][5], ad[i], b5);
            }
        }
        __syncthreads();
    }
    // stash gh tile to smem (reuse)
    #pragma unroll
    for (int i = 0; i < 4; i++)
        #pragma unroll
        for (int jj = 0; jj < 6; jj++) {
            float2 p = unpack2(acc[i][jj]);
            Cs[((ty << 2) + i) * 192 + tx * 12 + 2 * jj    ] = p.x;
            Cs[((ty << 2) + i) * 192 + tx * 12 + 2 * jj + 1] = p.y;
        }
    __syncthreads();
    // gates: 64 rows * 64 feats = 4096 elems, 16 per thread
    #pragma unroll
    for (int rep = 0; rep < 16; rep++) {
        int e = tid + rep * 256;
        int row = e >> 6, f = e & 63;
        int grow = r0 + row;
        if (grow < n) {
            float hr = Cs[row * 192 + f       ] + bhh[f       ];
            float hz = Cs[row * 192 + 64 + f  ] + bhh[64 + f  ];
            float hn = Cs[row * 192 + 128 + f ] + bhh[128 + f ];
            const float* gi = g_gi + ((size_t)t * n + grow) * 192;
            float r  = sigf(gi[f] + hr);
            float zg = sigf(gi[64 + f] + hz);
            float ng = tanhf(gi[128 + f] + r * hn);
            float ho = g_h[(size_t)grow * 64 + f];
            g_h[(size_t)grow * 64 + f] = (1.f - zg) * ng + zg * ho;
        }
    }
}

// ---------------- decoder: softplus(z @ z^T + b), symmetric, packed f32x2 FMA ----
__global__ void __launch_bounds__(256) k_decode(float* __restrict__ C, const float* __restrict__ dbias, int n) {
    int bj = blockIdx.x, bi = blockIdx.y;
    if (bj < bi) return;                         // symmetry: compute upper triangle only
    __shared__ float As[32 * 128];
    __shared__ float Bs[32 * 128];
    int i0 = bi * 128, j0 = bj * 128;
    int tid = threadIdx.x;
    int ty = tid >> 4, tx = tid & 15;
    unsigned long long acc[8][4];
    #pragma unroll
    for (int i = 0; i < 8; i++)
        #pragma unroll
        for (int jj = 0; jj < 4; jj++) acc[i][jj] = 0ULL;

    for (int k0 = 0; k0 < 64; k0 += 32) {
        {   // load A (z rows i0..i0+127, k chunk) transposed
            int row = tid >> 1, kb = (tid & 1) * 16;
            #pragma unroll
            for (int c = 0; c < 4; c++) {
                float4 v = make_float4(0.f, 0.f, 0.f, 0.f);
                if (i0 + row < n) v = *(const float4*)(g_h + (size_t)(i0 + row) * 64 + k0 + kb + c * 4);
                As[(kb + c * 4 + 0) * 128 + row] = v.x;
                As[(kb + c * 4 + 1) * 128 + row] = v.y;
                As[(kb + c * 4 + 2) * 128 + row] = v.z;
                As[(kb + c * 4 + 3) * 128 + row] = v.w;
            }
        }
        {   // load B (z rows j0..)
            int row = tid >> 1, kb = (tid & 1) * 16;
            #pragma unroll
            for (int c = 0; c < 4; c++) {
                float4 v = make_float4(0.f, 0.f, 0.f, 0.f);
                if (j0 + row < n) v = *(const float4*)(g_h + (size_t)(j0 + row) * 64 + k0 + kb + c * 4);
                Bs[(kb + c * 4 + 0) * 128 + row] = v.x;
                Bs[(kb + c * 4 + 1) * 128 + row] = v.y;
                Bs[(kb + c * 4 + 2) * 128 + row] = v.z;
                Bs[(kb + c * 4 + 3) * 128 + row] = v.w;
            }
        }
        __syncthreads();
        #pragma unroll
        for (int k = 0; k < 32; k++) {
            const float* ap = &As[k * 128 + (ty << 3)];
            float4 a0 = *(const float4*)ap;
            float4 a1 = *(const float4*)(ap + 4);
            unsigned long long ad[8] = { dup2(a0.x), dup2(a0.y), dup2(a0.z), dup2(a0.w),
                                         dup2(a1.x), dup2(a1.y), dup2(a1.z), dup2(a1.w) };
            const unsigned long long* bp = (const unsigned long long*)&Bs[k * 128 + (tx << 3)];
            unsigned long long b0 = bp[0], b1 = bp[1], b2 = bp[2], b3 = bp[3];
            #pragma unroll
            for (int i = 0; i < 8; i++) {
                fma2(acc[i][0], ad[i], b0);
                fma2(acc[i][1], ad[i], b1);
                fma2(acc[i][2], ad[i], b2);
                fma2(acc[i][3], ad[i], b3);
            }
        }
        __syncthreads();
    }
    float db = dbias[0];
    // softplus in place (keeps register pressure flat)
    #pragma unroll
    for (int i = 0; i < 8; i++)
        #pragma unroll
        for (int jj = 0; jj < 4; jj++) {
            float2 p = unpack2(acc[i][jj]);
            acc[i][jj] = pack2(softplusf(p.x + db), softplusf(p.y + db));
        }
    // normal store: rows i0+ty*8+i, cols j0+tx*8..+7
    int gj = j0 + (tx << 3);
    #pragma unroll
    for (int i = 0; i < 8; i++) {
        int gi_ = i0 + (ty << 3) + i;
        if (gi_ >= n) continue;
        float2 p0 = unpack2(acc[i][0]), p1 = unpack2(acc[i][1]);
        float2 p2 = unpack2(acc[i][2]), p3 = unpack2(acc[i][3]);
        float* cp = C + (size_t)gi_ * n + gj;
        if (gj + 8 <= n) {
            *(float4*)cp       = make_float4(p0.x, p0.y, p1.x, p1.y);
            *(float4*)(cp + 4) = make_float4(p2.x, p2.y, p3.x, p3.y);
        } else {
            float vals[8] = { p0.x, p0.y, p1.x, p1.y, p2.x, p2.y, p3.x, p3.y };
            for (int jj = 0; jj < 8; jj++)
                if (gj + jj < n) cp[jj] = vals[jj];
        }
    }
    // mirror store for off-diagonal blocks: C[j][i] = C[i][j]
    if (bi != bj) {
        int ci = i0 + (ty << 3);                 // column base in mirror
        #pragma unroll
        for (int j = 0; j < 8; j++) {
            int r2 = j0 + (tx << 3) + j;
            if (r2 >= n) continue;
            float f[8];
            #pragma unroll
            for (int i = 0; i < 8; i++) {
                float2 p = unpack2(acc[i][j >> 1]);
                f[i] = (j & 1) ? p.y : p.x;
            }
            float* cp = C + (size_t)r2 * n + ci;
            if (ci + 8 <= n) {
                *(float4*)cp       = make_float4(f[0], f[1], f[2], f[3]);
                *(float4*)(cp + 4) = make_float4(f[4], f[5], f[6], f[7]);
            } else {
                for (int i = 0; i < 8; i++)
                    if (ci + i < n) cp[i] = f[i];
            }
        }
    }
}

__global__ void k_copyz(float* __restrict__ out, int n) {
    int i = blockIdx.x * blockDim.x + threadIdx.x;
    if (i < n * 64) out[(size_t)n * n + i] = g_h[i];
}

// ---------------- host ----------------
extern "C" void kernel_launch(void* const* d_in, const int* in_sizes, int n_in,
                              void* d_out, int out_size) {
    const float* x     = (const float*)d_in[0];
    const int*   ei    = (const int*)d_in[1];      // int32! (JAX demotes int64)
    const float* ew    = (const float*)d_in[2];
    const float* W1    = (const float*)d_in[3];
    const float* b1    = (const float*)d_in[4];
    const float* W2    = (const float*)d_in[5];
    const float* b2    = (const float*)d_in[6];
    const float* Wih   = (const float*)d_in[7];
    const float* Whh   = (const float*)d_in[8];
    const float* bih   = (const float*)d_in[9];
    const float* bhh   = (const float*)d_in[10];
    const float* dbias = (const float*)d_in[11];
    float* out = (float*)d_out;

    int E = in_sizes[2];
    int N = in_sizes[0] / (T_STEPS * IN_DIM);
    if (N > NMAX) N = NMAX;                        // hard guard: never OOB scratch
    if (E > EDGEMAX - N) E = EDGEMAX - N;
    int M = T_STEPS * N;

    float *p_xagg, *p_H, *p_M2, *p_zseq, *p_gi, *p_h, *p_WTih, *p_WThh;
    cudaGetSymbolAddress((void**)&p_xagg, g_xagg);
    cudaGetSymbolAddress((void**)&p_H,    g_H);
    cudaGetSymbolAddress((void**)&p_M2,   g_M2);
    cudaGetSymbolAddress((void**)&p_zseq, g_zseq);
    cudaGetSymbolAddress((void**)&p_gi,   g_gi);
    cudaGetSymbolAddress((void**)&p_h,    g_h);
    cudaGetSymbolAddress((void**)&p_WTih, g_WTih);
    cudaGetSymbolAddress((void**)&p_WThh, g_WThh);

    const int B = 256;
    // graph preprocessing
    k_init  <<<(N + B - 1) / B, B>>>(N);
    k_degcnt<<<(E + B - 1) / B, B>>>(ei, ew, E, N);
    k_dinv  <<<(N + B - 1) / B, B>>>(N);
    k_scan  <<<1, 1024>>>(N);
    k_fill  <<<(E + N + B - 1) / B, B>>>(ei, ew, E, N);

    // encoder: AX -> (AX)W1+b1,relu -> HW2 -> A(HW2)+b2
    int aggBlocks = (N * T_STEPS * 32 + B - 1) / B;
    k_agg <<<aggBlocks, B>>>(x, p_xagg, nullptr, N);
    k_gemm<<<dim3((M + 63) / 64, HID_DIM / 64), B>>>(p_xagg, W1, b1, p_H, M, IN_DIM, HID_DIM, 1);
    k_gemm<<<dim3((M + 63) / 64, EMB / 64),     B>>>(p_H, W2, nullptr, p_M2, M, HID_DIM, EMB, 0);
    k_agg <<<aggBlocks, B>>>(p_M2, p_zseq, b2, N);

    // GRU
    k_transpose<<<(EMB * G3 + B - 1) / B, B>>>(Wih, p_WTih);
    k_transpose<<<(EMB * G3 + B - 1) / B, B>>>(Whh, p_WThh);
    k_gemm<<<dim3((M + 63) / 64, G3 / 64), B>>>(p_zseq, p_WTih, bih, p_gi, M, EMB, G3, 0);
    k_zero<<<(N * EMB + B - 1) / B, B>>>(p_h, N * EMB);
    for (int t = 0; t < T_STEPS; t++)
        k_gru<<<(N + 63) / 64, B>>>(bhh, N, t);

    // decoder + z output
    int gb = (N + 127) / 128;
    k_decode<<<dim3(gb, gb), B>>>(out, dbias, N);
    k_copyz <<<(N * EMB + B - 1) / B, B>>>(out, N);
}

// round 8
// speedup vs baseline: 1.4768x; 1.3438x over previous
#include <cuda_runtime.h>
#include <cuda_fp16.h>
#include <cstdint>

#define T_STEPS 12
#define IN_DIM  64
#define HID_DIM 128
#define EMB     64
#define G3      192

#define NMAX    10240
#define EDGEMAX 360448   /* > E + N */

// ---------------- scratch (static __device__, no allocations) ----------------
__device__ float  g_deg [NMAX];
__device__ float  g_dinv[NMAX];
__device__ int    g_cnt [NMAX];
__device__ int    g_off [NMAX + 1];
__device__ int    g_cur [NMAX];
__device__ int2   g_ce  [EDGEMAX];                      // (row, norm-as-int)
__device__ __half g_xh  [(size_t)T_STEPS * NMAX * IN_DIM];
__device__ float  g_xagg[(size_t)T_STEPS * NMAX * IN_DIM];
__device__ float  g_H   [(size_t)T_STEPS * NMAX * HID_DIM];
__device__ __half g_M2h [(size_t)T_STEPS * NMAX * EMB];
__device__ float  g_zseq[(size_t)T_STEPS * NMAX * EMB];
__device__ float  g_gi  [(size_t)T_STEPS * NMAX * G3];
__device__ float  g_h   [(size_t)NMAX * EMB];
__device__ float  g_WTih[EMB * G3];
__device__ float  g_WThh[EMB * G3];

// ---------------- small helpers ----------------
__device__ __forceinline__ float sigf(float x) { return 1.f / (1.f + __expf(-x)); }

__device__ __forceinline__ float softplusf(float x) {
    float u = __expf(-fabsf(x));                 // = exp(x) when x<0
    float r = fmaxf(x, 0.f) + __logf(1.f + u);
    if (x < -15.f) r = u;                        // avoid 1+u==1 rounding
    return r;
}

__device__ __forceinline__ unsigned long long dup2(float a) {
    unsigned long long r;
    asm("mov.b64 %0, {%1, %1};" : "=l"(r) : "f"(a));
    return r;
}
__device__ __forceinline__ unsigned long long pack2(float lo, float hi) {
    unsigned long long r;
    asm("mov.b64 %0, {%1, %2};" : "=l"(r) : "f"(lo), "f"(hi));
    return r;
}
__device__ __forceinline__ float2 unpack2(unsigned long long v) {
    float lo, hi;
    asm("mov.b64 {%0, %1}, %2;" : "=f"(lo), "=f"(hi) : "l"(v));
    return make_float2(lo, hi);
}
__device__ __forceinline__ void fma2(unsigned long long& d, unsigned long long a, unsigned long long b) {
    asm("fma.rn.f32x2 %0, %1, %2, %0;" : "+l"(d) : "l"(a), "l"(b));
}

// ---------------- graph preprocessing ----------------
__global__ void k_init(int n) {
    int i = blockIdx.x * blockDim.x + threadIdx.x;
    if (i < n) { g_deg[i] = 1.f; g_cnt[i] = 1; }   // self-loop weight/count
}

// edge_index is INT32 (JAX without x64 demotes int64 -> int32): layout [2, E]
__global__ void k_degcnt(const int* __restrict__ ei, const float* __restrict__ ew, int E, int n) {
    int e = blockIdx.x * blockDim.x + threadIdx.x;
    if (e < E) {
        int c = ei[E + e];
        c = min(max(c, 0), n - 1);               // defensive clamp
        atomicAdd(&g_deg[c], ew[e]);
        atomicAdd(&g_cnt[c], 1);
    }
}

__global__ void k_dinv(int n) {
    int i = blockIdx.x * blockDim.x + threadIdx.x;
    if (i < n) {
        float d = g_deg[i];
        g_dinv[i] = (d > 0.f) ? rsqrtf(d) : 0.f;
    }
}

__global__ void k_scan(int n) {      // <<<1, 1024>>>
    __shared__ int sums[1024];
    int tid = threadIdx.x;
    int per = (n + 1023) / 1024;
    int start = tid * per;
    int end   = min(start + per, n);
    int s = 0;
    for (int i = start; i < end; i++) s += g_cnt[i];
    sums[tid] = s;
    __syncthreads();
    for (int d = 1; d < 1024; d <<= 1) {
        int v = 0;
        if (tid >= d) v = sums[tid - d];
        __syncthreads();
        if (tid >= d) sums[tid] += v;
        __syncthreads();
    }
    int base = (tid == 0) ? 0 : sums[tid - 1];
    for (int i = start; i < end; i++) {
        g_off[i] = base; g_cur[i] = base;
        base += g_cnt[i];
    }
    if (tid == 1023) g_off[n] = sums[1023];
}

__global__ void k_fill(const int* __restrict__ ei, const float* __restrict__ ew, int E, int n) {
    int e = blockIdx.x * blockDim.x + threadIdx.x;
    int total = E + n;
    if (e >= total) return;
    int r, c; float w;
    if (e < E) {
        r = ei[e]; c = ei[E + e]; w = ew[e];
        r = min(max(r, 0), n - 1);
        c = min(max(c, 0), n - 1);
    }
    else       { r = c = e - E; w = 1.f; }
    float norm = g_dinv[r] * w * g_dinv[c];
    int pos = atomicAdd(&g_cur[c], 1);
    pos = min(max(pos, 0), EDGEMAX - 1);         // defensive clamp
    g_ce[pos] = make_int2(r, __float_as_int(norm));
}

// ---------------- float -> half conversion (paired) ----------------
__global__ void k_tohalf(const float* __restrict__ src, __half* __restrict__ dst, int cnt2) {
    int i = blockIdx.x * blockDim.x + threadIdx.x;
    if (i < cnt2) {
        float2 v = ((const float2*)src)[i];
        ((__half2*)dst)[i] = __float22half2_rn(v);
    }
}

// ---------------- aggregation (fp16 gather, fp32 accumulate), warp per (node,t) ----
__global__ void k_agg_h(const __half2* __restrict__ in, float* __restrict__ out,
                        const float* __restrict__ bias, int n) {
    int w    = (blockIdx.x * blockDim.x + threadIdx.x) >> 5;
    int lane = threadIdx.x & 31;
    if (w >= n * T_STEPS) return;
    int t = w / n, nd = w - t * n;
    int s = g_off[nd], e = g_off[nd + 1];
    const __half2* base = in + (size_t)t * n * 32;
    float a0 = 0.f, a1 = 0.f;
    int j = s;
    for (; j + 3 < e; j += 4) {                  // 4-way unroll for MLP
        int2 p0 = g_ce[j], p1 = g_ce[j + 1], p2 = g_ce[j + 2], p3 = g_ce[j + 3];
        float2 v0 = __half22float2(base[(size_t)p0.x * 32 + lane]);
        float2 v1 = __half22float2(base[(size_t)p1.x * 32 + lane]);
        float2 v2 = __half22float2(base[(size_t)p2.x * 32 + lane]);
        float2 v3 = __half22float2(base[(size_t)p3.x * 32 + lane]);
        float w0 = __int_as_float(p0.y), w1 = __int_as_float(p1.y);
        float w2 = __int_as_float(p2.y), w3 = __int_as_float(p3.y);
        a0 = fmaf(w0, v0.x, a0); a1 = fmaf(w0, v0.y, a1);
        a0 = fmaf(w1, v1.x, a0); a1 = fmaf(w1, v1.y, a1);
        a0 = fmaf(w2, v2.x, a0); a1 = fmaf(w2, v2.y, a1);
        a0 = fmaf(w3, v3.x, a0); a1 = fmaf(w3, v3.y, a1);
    }
    for (; j < e; j++) {
        int2 p0 = g_ce[j];
        float2 v0 = __half22float2(base[(size_t)p0.x * 32 + lane]);
        float w0 = __int_as_float(p0.y);
        a0 = fmaf(w0, v0.x, a0); a1 = fmaf(w0, v0.y, a1);
    }
    if (bias) { a0 += bias[lane * 2]; a1 += bias[lane * 2 + 1]; }
    float2* o = (float2*)(out + ((size_t)t * n + nd) * 64);
    o[lane] = make_float2(a0, a1);
}

// ---------------- generic tiled GEMM: C[M,NC] = act(A[M,K] @ B[K,NC] + bias) ----------------
// half_out: store as __half instead of float
__global__ void __launch_bounds__(256) k_gemm(const float* __restrict__ A, const float* __restrict__ B,
                                              const float* __restrict__ bias, void* __restrict__ Cv,
                                              int M, int K, int NC, int relu, int half_out) {
    __shared__ float As[16][68];
    __shared__ float Bs[16][68];
    int r0 = blockIdx.x * 64, c0 = blockIdx.y * 64;
    int tid = threadIdx.x;
    int ty = tid >> 4, tx = tid & 15;
    unsigned long long acc[4][2];
    #pragma unroll
    for (int i = 0; i < 4; i++) { acc[i][0] = 0ULL; acc[i][1] = 0ULL; }
    for (int k0 = 0; k0 < K; k0 += 16) {
        {   // A tile -> transposed
            int m = tid >> 2, kb = (tid & 3) << 2;
            float4 v = make_float4(0.f, 0.f, 0.f, 0.f);
            if (r0 + m < M) v = *(const float4*)(A + (size_t)(r0 + m) * K + k0 + kb);
            As[kb + 0][m] = v.x; As[kb + 1][m] = v.y; As[kb + 2][m] = v.z; As[kb + 3][m] = v.w;
        }
        {   // B tile
            int k = tid >> 4, nb = (tid & 15) << 2;
            *(float4*)&Bs[k][nb] = *(const float4*)(B + (size_t)(k0 + k) * NC + c0 + nb);
        }
        __syncthreads();
        #pragma unroll
        for (int k = 0; k < 16; k++) {
            float4 a = *(const float4*)&As[k][ty << 2];
            unsigned long long ad[4] = { dup2(a.x), dup2(a.y), dup2(a.z), dup2(a.w) };
            const unsigned long long* bp = (const unsigned long long*)&Bs[k][tx << 2];
            unsigned long long b0 = bp[0], b1 = bp[1];
            #pragma unroll
            for (int i = 0; i < 4; i++) {
                fma2(acc[i][0], ad[i], b0);
                fma2(acc[i][1], ad[i], b1);
            }
        }
        __syncthreads();
    }
    #pragma unroll
    for (int i = 0; i < 4; i++) {
        int row = r0 + (ty << 2) + i;
        if (row >= M) continue;
        float2 p0 = unpack2(acc[i][0]);
        float2 p1 = unpack2(acc[i][1]);
        float vv[4] = { p0.x, p0.y, p1.x, p1.y };
        #pragma unroll
        for (int jj = 0; jj < 4; jj++) {
            int col = c0 + (tx << 2) + jj;
            float v = vv[jj];
            if (bias) v += bias[col];
            if (relu) v = fmaxf(v, 0.f);
            if (half_out) ((__half*)Cv)[(size_t)row * NC + col] = __float2half_rn(v);
            else          ((float*)Cv)[(size_t)row * NC + col] = v;
        }
    }
}

// ---------------- weight transpose [192,64] -> [64,192] ----------------
__global__ void k_transpose(const float* __restrict__ in, float* __restrict__ out) {
    int i = blockIdx.x * blockDim.x + threadIdx.x;
    if (i < EMB * G3) {
        int k = i / G3, g = i - k * G3;
        out[i] = in[g * EMB + k];
    }
}

// ---------------- fully fused GRU: all 12 steps in one kernel ----------------
// Row-independence: h_new[i] depends only on h[i] and gi[t][i]; block-local loop.
// smem: Wh = W_hh^T [64][192] (48 KB) + ht [64(k)][68(m)] transposed h tile (17 KB)
#define GRU_SMEM_FLOATS (12288 + 64 * 68)
__global__ void __launch_bounds__(256) k_gru_all(const float* __restrict__ bhh, int n) {
    extern __shared__ float S[];
    float* Wh = S;                               // [64][192]
    float* ht = S + 12288;                       // [64][68]
    int r0 = blockIdx.x * 64;
    int tid = threadIdx.x;
    int ty = tid >> 4, tx = tid & 15;
    for (int i = tid; i < 12288; i += 256) Wh[i] = g_WThh[i];
    for (int i = tid; i < 64 * 68; i += 256) ht[i] = 0.f;
    // per-thread gate biases (f = tx*4 .. +3)
    float bh_r[4], bh_z[4], bh_n[4];
    #pragma unroll
    for (int q = 0; q < 4; q++) {
        bh_r[q] = bhh[(tx << 2) + q];
        bh_z[q] = bhh[64 + (tx << 2) + q];
        bh_n[q] = bhh[128 + (tx << 2) + q];
    }
    __syncthreads();

    for (int t = 0; t < T_STEPS; t++) {
        unsigned long long acc[4][6];
        #pragma unroll
        for (int i = 0; i < 4; i++)
            #pragma unroll
            for (int jj = 0; jj < 6; jj++) acc[i][jj] = 0ULL;
        #pragma unroll 8
        for (int k = 0; k < 64; k++) {
            float4 a = *(const float4*)&ht[k * 68 + (ty << 2)];
            unsigned long long ad[4] = { dup2(a.x), dup2(a.y), dup2(a.z), dup2(a.w) };
            const unsigned long long* br = (const unsigned long long*)&Wh[k * 192 + (tx << 2)];
            const unsigned long long* bz = (const unsigned long long*)&Wh[k * 192 + 64 + (tx << 2)];
            const unsigned long long* bn = (const unsigned long long*)&Wh[k * 192 + 128 + (tx << 2)];
            unsigned long long r0v = br[0], r1v = br[1];
            unsigned long long z0v = bz[0], z1v = bz[1];
            unsigned long long n0v = bn[0], n1v = bn[1];
            #pragma unroll
            for (int i = 0; i < 4; i++) {
                fma2(acc[i][0], ad[i], r0v);
                fma2(acc[i][1], ad[i], r1v);
                fma2(acc[i][2], ad[i], z0v);
                fma2(acc[i][3], ad[i], z1v);
                fma2(acc[i][4], ad[i], n0v);
                fma2(acc[i][5], ad[i], n1v);
            }
        }
        __syncthreads();                         // all ht reads complete
        #pragma unroll
        for (int i = 0; i < 4; i++) {
            int row = (ty << 2) + i;
            int grow = r0 + row;
            if (grow < n) {
                const float* gip = g_gi + ((size_t)t * n + grow) * 192;
                float4 gr = *(const float4*)(gip + (tx << 2));
                float4 gz = *(const float4*)(gip + 64 + (tx << 2));
                float4 gn = *(const float4*)(gip + 128 + (tx << 2));
                float2 hr01 = unpack2(acc[i][0]), hr23 = unpack2(acc[i][1]);
                float2 hz01 = unpack2(acc[i][2]), hz23 = unpack2(acc[i][3]);
                float2 hn01 = unpack2(acc[i][4]), hn23 = unpack2(acc[i][5]);
                float hrq[4] = { hr01.x, hr01.y, hr23.x, hr23.y };
                float hzq[4] = { hz01.x, hz01.y, hz23.x, hz23.y };
                float hnq[4] = { hn01.x, hn01.y, hn23.x, hn23.y };
                float grq[4] = { gr.x, gr.y, gr.z, gr.w };
                float gzq[4] = { gz.x, gz.y, gz.z, gz.w };
                float gnq[4] = { gn.x, gn.y, gn.z, gn.w };
                #pragma unroll
                for (int q = 0; q < 4; q++) {
                    int f = (tx << 2) + q;
                    float r  = sigf(grq[q] + hrq[q] + bh_r[q]);
                    float zg = sigf(gzq[q] + hzq[q] + bh_z[q]);
                    float ng = tanhf(gnq[q] + r * (hnq[q] + bh_n[q]));
                    float ho = ht[f * 68 + row];
                    ht[f * 68 + row] = (1.f - zg) * ng + zg * ho;
                }
            }
        }
        __syncthreads();                         // updates visible before next step
    }
    // write back h (for decoder)
    for (int e = tid; e < 4096; e += 256) {
        int row = e >> 6, f = e & 63;
        if (r0 + row < n) g_h[(size_t)(r0 + row) * 64 + f] = ht[f * 68 + row];
    }
}

// ---------------- decoder: softplus(z @ z^T + b), symmetric, packed f32x2 FMA ----
__global__ void __launch_bounds__(256) k_decode(float* __restrict__ C, const float* __restrict__ dbias, int n) {
    int bj = blockIdx.x, bi = blockIdx.y;
    if (bj < bi) return;                         // symmetry: compute upper triangle only
    __shared__ float As[32 * 128];
    __shared__ float Bs[32 * 128];
    int i0 = bi * 128, j0 = bj * 128;
    int tid = threadIdx.x;
    int ty = tid >> 4, tx = tid & 15;
    unsigned long long acc[8][4];
    #pragma unroll
    for (int i = 0; i < 8; i++)
        #pragma unroll
        for (int jj = 0; jj < 4; jj++) acc[i][jj] = 0ULL;

    for (int k0 = 0; k0 < 64; k0 += 32) {
        {   // load A (z rows i0..i0+127, k chunk) transposed
            int row = tid >> 1, kb = (tid & 1) * 16;
            #pragma unroll
            for (int c = 0; c < 4; c++) {
                float4 v = make_float4(0.f, 0.f, 0.f, 0.f);
                if (i0 + row < n) v = *(const float4*)(g_h + (size_t)(i0 + row) * 64 + k0 + kb + c * 4);
                As[(kb + c * 4 + 0) * 128 + row] = v.x;
                As[(kb + c * 4 + 1) * 128 + row] = v.y;
                As[(kb + c * 4 + 2) * 128 + row] = v.z;
                As[(kb + c * 4 + 3) * 128 + row] = v.w;
            }
        }
        {   // load B (z rows j0..)
            int row = tid >> 1, kb = (tid & 1) * 16;
            #pragma unroll
            for (int c = 0; c < 4; c++) {
                float4 v = make_float4(0.f, 0.f, 0.f, 0.f);
                if (j0 + row < n) v = *(const float4*)(g_h + (size_t)(j0 + row) * 64 + k0 + kb + c * 4);
                Bs[(kb + c * 4 + 0) * 128 + row] = v.x;
                Bs[(kb + c * 4 + 1) * 128 + row] = v.y;
                Bs[(kb + c * 4 + 2) * 128 + row] = v.z;
                Bs[(kb + c * 4 + 3) * 128 + row] = v.w;
            }
        }
        __syncthreads();
        #pragma unroll
        for (int k = 0; k < 32; k++) {
            const float* ap = &As[k * 128 + (ty << 3)];
            float4 a0 = *(const float4*)ap;
            float4 a1 = *(const float4*)(ap + 4);
            unsigned long long ad[8] = { dup2(a0.x), dup2(a0.y), dup2(a0.z), dup2(a0.w),
                                         dup2(a1.x), dup2(a1.y), dup2(a1.z), dup2(a1.w) };
            const unsigned long long* bp = (const unsigned long long*)&Bs[k * 128 + (tx << 3)];
            unsigned long long b0 = bp[0], b1 = bp[1], b2 = bp[2], b3 = bp[3];
            #pragma unroll
            for (int i = 0; i < 8; i++) {
                fma2(acc[i][0], ad[i], b0);
                fma2(acc[i][1], ad[i], b1);
                fma2(acc[i][2], ad[i], b2);
                fma2(acc[i][3], ad[i], b3);
            }
        }
        __syncthreads();
    }
    float db = dbias[0];
    // softplus in place (keeps register pressure flat)
    #pragma unroll
    for (int i = 0; i < 8; i++)
        #pragma unroll
        for (int jj = 0; jj < 4; jj++) {
            float2 p = unpack2(acc[i][jj]);
            acc[i][jj] = pack2(softplusf(p.x + db), softplusf(p.y + db));
        }
    // normal store: rows i0+ty*8+i, cols j0+tx*8..+7
    int gj = j0 + (tx << 3);
    #pragma unroll
    for (int i = 0; i < 8; i++) {
        int gi_ = i0 + (ty << 3) + i;
        if (gi_ >= n) continue;
        float2 p0 = unpack2(acc[i][0]), p1 = unpack2(acc[i][1]);
        float2 p2 = unpack2(acc[i][2]), p3 = unpack2(acc[i][3]);
        float* cp = C + (size_t)gi_ * n + gj;
        if (gj + 8 <= n) {
            *(float4*)cp       = make_float4(p0.x, p0.y, p1.x, p1.y);
            *(float4*)(cp + 4) = make_float4(p2.x, p2.y, p3.x, p3.y);
        } else {
            float vals[8] = { p0.x, p0.y, p1.x, p1.y, p2.x, p2.y, p3.x, p3.y };
            for (int jj = 0; jj < 8; jj++)
                if (gj + jj < n) cp[jj] = vals[jj];
        }
    }
    // mirror store for off-diagonal blocks: C[j][i] = C[i][j]
    if (bi != bj) {
        int ci = i0 + (ty << 3);                 // column base in mirror
        #pragma unroll
        for (int j = 0; j < 8; j++) {
            int r2 = j0 + (tx << 3) + j;
            if (r2 >= n) continue;
            float f[8];
            #pragma unroll
            for (int i = 0; i < 8; i++) {
                float2 p = unpack2(acc[i][j >> 1]);
                f[i] = (j & 1) ? p.y : p.x;
            }
            float* cp = C + (size_t)r2 * n + ci;
            if (ci + 8 <= n) {
                *(float4*)cp       = make_float4(f[0], f[1], f[2], f[3]);
                *(float4*)(cp + 4) = make_float4(f[4], f[5], f[6], f[7]);
            } else {
                for (int i = 0; i < 8; i++)
                    if (ci + i < n) cp[i] = f[i];
            }
        }
    }
}

__global__ void k_copyz(float* __restrict__ out, int n) {
    int i = blockIdx.x * blockDim.x + threadIdx.x;
    if (i < n * 64) out[(size_t)n * n + i] = g_h[i];
}

// ---------------- host ----------------
extern "C" void kernel_launch(void* const* d_in, const int* in_sizes, int n_in,
                              void* d_out, int out_size) {
    const float* x     = (const float*)d_in[0];
    const int*   ei    = (const int*)d_in[1];      // int32! (JAX demotes int64)
    const float* ew    = (const float*)d_in[2];
    const float* W1    = (const float*)d_in[3];
    const float* b1    = (const float*)d_in[4];
    const float* W2    = (const float*)d_in[5];
    const float* b2    = (const float*)d_in[6];
    const float* Wih   = (const float*)d_in[7];
    const float* Whh   = (const float*)d_in[8];
    const float* bih   = (const float*)d_in[9];
    const float* bhh   = (const float*)d_in[10];
    const float* dbias = (const float*)d_in[11];
    float* out = (float*)d_out;

    int E = in_sizes[2];
    int N = in_sizes[0] / (T_STEPS * IN_DIM);
    if (N > NMAX) N = NMAX;                        // hard guard: never OOB scratch
    if (E > EDGEMAX - N) E = EDGEMAX - N;
    int M = T_STEPS * N;

    float  *p_xagg, *p_H, *p_zseq, *p_gi, *p_WTih, *p_WThh;
    __half *p_xh, *p_M2h;
    cudaGetSymbolAddress((void**)&p_xh,   g_xh);
    cudaGetSymbolAddress((void**)&p_xagg, g_xagg);
    cudaGetSymbolAddress((void**)&p_H,    g_H);
    cudaGetSymbolAddress((void**)&p_M2h,  g_M2h);
    cudaGetSymbolAddress((void**)&p_zseq, g_zseq);
    cudaGetSymbolAddress((void**)&p_gi,   g_gi);
    cudaGetSymbolAddress((void**)&p_WTih, g_WTih);
    cudaGetSymbolAddress((void**)&p_WThh, g_WThh);

    static int smem_set = 0;
    if (!smem_set) {
        cudaFuncSetAttribute(k_gru_all, cudaFuncAttributeMaxDynamicSharedMemorySize,
                             GRU_SMEM_FLOATS * (int)sizeof(float));
        smem_set = 1;
    }

    const int B = 256;
    // graph preprocessing
    k_init  <<<(N + B - 1) / B, B>>>(N);
    k_degcnt<<<(E + B - 1) / B, B>>>(ei, ew, E, N);
    k_dinv  <<<(N + B - 1) / B, B>>>(N);
    k_scan  <<<1, 1024>>>(N);
    k_fill  <<<(E + N + B - 1) / B, B>>>(ei, ew, E, N);

    // encoder: AX -> (AX)W1+b1,relu -> HW2 (half) -> A(HW2)+b2
    int aggBlocks = (N * T_STEPS * 32 + B - 1) / B;
    k_tohalf<<<(M * 32 + B - 1) / B, B>>>(x, p_xh, M * 32);
    k_agg_h <<<aggBlocks, B>>>((const __half2*)p_xh, p_xagg, nullptr, N);
    k_gemm  <<<dim3((M + 63) / 64, HID_DIM / 64), B>>>(p_xagg, W1, b1, p_H, M, IN_DIM, HID_DIM, 1, 0);
    k_gemm  <<<dim3((M + 63) / 64, EMB / 64),     B>>>(p_H, W2, nullptr, p_M2h, M, HID_DIM, EMB, 0, 1);
    k_agg_h <<<aggBlocks, B>>>((const __half2*)p_M2h, p_zseq, b2, N);

    // GRU
    k_transpose<<<(EMB * G3 + B - 1) / B, B>>>(Wih, p_WTih);
    k_transpose<<<(EMB * G3 + B - 1) / B, B>>>(Whh, p_WThh);
    k_gemm<<<dim3((M + 63) / 64, G3 / 64), B>>>(p_zseq, p_WTih, bih, p_gi, M, EMB, G3, 0, 0);
    k_gru_all<<<(N + 63) / 64, B, GRU_SMEM_FLOATS * sizeof(float)>>>(bhh, N);

    // decoder + z output
    int gb = (N + 127) / 128;
    k_decode<<<dim3(gb, gb), B>>>(out, dbias, N);
    k_copyz <<<(N * EMB + B - 1) / B, B>>>(out, N);
}

// round 9
// speedup vs baseline: 1.9211x; 1.3008x over previous
#include <cuda_runtime.h>
#include <cuda_fp16.h>
#include <cstdint>

#define T_STEPS 12
#define IN_DIM  64
#define HID_DIM 128
#define EMB     64
#define G3      192

#define NMAX    10240
#define EDGEMAX 360448   /* > E + N */

// ---------------- scratch (static __device__, no allocations) ----------------
__device__ float  g_deg [NMAX];
__device__ float  g_dinv[NMAX];
__device__ int    g_cnt [NMAX];
__device__ int    g_off [NMAX + 1];
__device__ int    g_cur [NMAX];
__device__ int2   g_ce  [EDGEMAX];                      // (row, norm-as-int)
__device__ __half g_xh  [(size_t)T_STEPS * NMAX * IN_DIM];
__device__ float  g_xagg[(size_t)T_STEPS * NMAX * IN_DIM];
__device__ __half g_M2h [(size_t)T_STEPS * NMAX * EMB];
__device__ float  g_zseq[(size_t)T_STEPS * NMAX * EMB];
__device__ __half g_gih [(size_t)T_STEPS * NMAX * G3];
__device__ __half g_hh  [(size_t)NMAX * EMB];
__device__ float  g_WTih[EMB * G3];
__device__ float  g_WThh[EMB * G3];

// ---------------- small helpers ----------------
__device__ __forceinline__ float sigf(float x) { return 1.f / (1.f + __expf(-x)); }

__device__ __forceinline__ float softplusf(float x) {
    float u = __expf(-fabsf(x));                 // = exp(x) when x<0
    float r = fmaxf(x, 0.f) + __logf(1.f + u);
    if (x < -15.f) r = u;                        // avoid 1+u==1 rounding
    return r;
}

__device__ __forceinline__ unsigned long long dup2(float a) {
    unsigned long long r;
    asm("mov.b64 %0, {%1, %1};" : "=l"(r) : "f"(a));
    return r;
}
__device__ __forceinline__ float2 unpack2(unsigned long long v) {
    float lo, hi;
    asm("mov.b64 {%0, %1}, %2;" : "=f"(lo), "=f"(hi) : "l"(v));
    return make_float2(lo, hi);
}
__device__ __forceinline__ void fma2(unsigned long long& d, unsigned long long a, unsigned long long b) {
    asm("fma.rn.f32x2 %0, %1, %2, %0;" : "+l"(d) : "l"(a), "l"(b));
}

// ---------------- graph preprocessing ----------------
__global__ void k_init(int n) {
    int i = blockIdx.x * blockDim.x + threadIdx.x;
    if (i < n) { g_deg[i] = 1.f; g_cnt[i] = 1; }   // self-loop weight/count
}

// edge_index is INT32 (JAX without x64 demotes int64 -> int32): layout [2, E]
__global__ void k_degcnt(const int* __restrict__ ei, const float* __restrict__ ew, int E, int n) {
    int e = blockIdx.x * blockDim.x + threadIdx.x;
    if (e < E) {
        int c = ei[E + e];
        c = min(max(c, 0), n - 1);               // defensive clamp
        atomicAdd(&g_deg[c], ew[e]);
        atomicAdd(&g_cnt[c], 1);
    }
}

__global__ void k_dinv(int n) {
    int i = blockIdx.x * blockDim.x + threadIdx.x;
    if (i < n) {
        float d = g_deg[i];
        g_dinv[i] = (d > 0.f) ? rsqrtf(d) : 0.f;
    }
}

__global__ void k_scan(int n) {      // <<<1, 1024>>>
    __shared__ int sums[1024];
    int tid = threadIdx.x;
    int per = (n + 1023) / 1024;
    int start = tid * per;
    int end   = min(start + per, n);
    int s = 0;
    for (int i = start; i < end; i++) s += g_cnt[i];
    sums[tid] = s;
    __syncthreads();
    for (int d = 1; d < 1024; d <<= 1) {
        int v = 0;
        if (tid >= d) v = sums[tid - d];
        __syncthreads();
        if (tid >= d) sums[tid] += v;
        __syncthreads();
    }
    int base = (tid == 0) ? 0 : sums[tid - 1];
    for (int i = start; i < end; i++) {
        g_off[i] = base; g_cur[i] = base;
        base += g_cnt[i];
    }
    if (tid == 1023) g_off[n] = sums[1023];
}

__global__ void k_fill(const int* __restrict__ ei, const float* __restrict__ ew, int E, int n) {
    int e = blockIdx.x * blockDim.x + threadIdx.x;
    int total = E + n;
    if (e >= total) return;
    int r, c; float w;
    if (e < E) {
        r = ei[e]; c = ei[E + e]; w = ew[e];
        r = min(max(r, 0), n - 1);
        c = min(max(c, 0), n - 1);
    }
    else       { r = c = e - E; w = 1.f; }
    float norm = g_dinv[r] * w * g_dinv[c];
    int pos = atomicAdd(&g_cur[c], 1);
    pos = min(max(pos, 0), EDGEMAX - 1);         // defensive clamp
    g_ce[pos] = make_int2(r, __float_as_int(norm));
}

// ---------------- float -> half conversion (paired) ----------------
__global__ void k_tohalf(const float* __restrict__ src, __half* __restrict__ dst, int cnt2) {
    int i = blockIdx.x * blockDim.x + threadIdx.x;
    if (i < cnt2) {
        float2 v = ((const float2*)src)[i];
        ((__half2*)dst)[i] = __float22half2_rn(v);
    }
}

// ---------------- aggregation (fp16 gather, fp32 accumulate), warp per node, y = t ----
__global__ void k_agg_h(const __half2* __restrict__ in, float* __restrict__ out,
                        const float* __restrict__ bias, int n) {
    int nd   = (blockIdx.x * blockDim.x + threadIdx.x) >> 5;
    int lane = threadIdx.x & 31;
    int t    = blockIdx.y;
    if (nd >= n) return;
    int s = g_off[nd], e = g_off[nd + 1];
    const __half2* base = in + (size_t)t * n * 32;
    float a0 = 0.f, a1 = 0.f;
    int j = s;
    for (; j + 3 < e; j += 4) {                  // 4-way unroll for MLP
        int2 p0 = g_ce[j], p1 = g_ce[j + 1], p2 = g_ce[j + 2], p3 = g_ce[j + 3];
        float2 v0 = __half22float2(base[(size_t)p0.x * 32 + lane]);
        float2 v1 = __half22float2(base[(size_t)p1.x * 32 + lane]);
        float2 v2 = __half22float2(base[(size_t)p2.x * 32 + lane]);
        float2 v3 = __half22float2(base[(size_t)p3.x * 32 + lane]);
        float w0 = __int_as_float(p0.y), w1 = __int_as_float(p1.y);
        float w2 = __int_as_float(p2.y), w3 = __int_as_float(p3.y);
        a0 = fmaf(w0, v0.x, a0); a1 = fmaf(w0, v0.y, a1);
        a0 = fmaf(w1, v1.x, a0); a1 = fmaf(w1, v1.y, a1);
        a0 = fmaf(w2, v2.x, a0); a1 = fmaf(w2, v2.y, a1);
        a0 = fmaf(w3, v3.x, a0); a1 = fmaf(w3, v3.y, a1);
    }
    for (; j < e; j++) {
        int2 p0 = g_ce[j];
        float2 v0 = __half22float2(base[(size_t)p0.x * 32 + lane]);
        float w0 = __int_as_float(p0.y);
        a0 = fmaf(w0, v0.x, a0); a1 = fmaf(w0, v0.y, a1);
    }
    if (bias) { a0 += bias[lane * 2]; a1 += bias[lane * 2 + 1]; }
    float2* o = (float2*)(out + ((size_t)t * n + nd) * 64);
    o[lane] = make_float2(a0, a1);
}

// ---------------- fused encoder GEMMs: M2 = relu(A@W1+b1)@W2, fp16 out ----------------
// smem: S[0..1088) As (stage1) / B2s (stage2); [1088..3200) B1s[16][132]; [3200..11904) Ht[128][68]
__global__ void __launch_bounds__(256) k_enc(const float* __restrict__ A, const float* __restrict__ W1,
                                             const float* __restrict__ b1, const float* __restrict__ W2,
                                             __half* __restrict__ M2h, int M) {
    __shared__ float S[11904];
    float* As  = S;              // [16][68]
    float* B2s = S;              // [16][68] (reuse)
    float* B1s = S + 1088;       // [16][132]
    float* Ht  = S + 3200;       // [128][68], row-quad swizzled by tx
    int r0 = blockIdx.x * 64;
    int tid = threadIdx.x;
    int ty = tid >> 4, tx = tid & 15;

    // ---- stage 1: H = relu(A@W1 + b1), acc 4 rows x 8 cols ----
    unsigned long long acc1[4][4];
    #pragma unroll
    for (int i = 0; i < 4; i++)
        #pragma unroll
        for (int jj = 0; jj < 4; jj++) acc1[i][jj] = 0ULL;
    for (int k0 = 0; k0 < 64; k0 += 16) {
        {   // A tile transposed
            int m = tid >> 2, kb = (tid & 3) << 2;
            float4 v = make_float4(0.f, 0.f, 0.f, 0.f);
            if (r0 + m < M) v = *(const float4*)(A + (size_t)(r0 + m) * 64 + k0 + kb);
            As[(kb + 0) * 68 + m] = v.x; As[(kb + 1) * 68 + m] = v.y;
            As[(kb + 2) * 68 + m] = v.z; As[(kb + 3) * 68 + m] = v.w;
        }
        {   // W1 tile: 16 x 128
            int k = tid >> 4, nb = (tid & 15) << 3;
            *(float4*)&B1s[k * 132 + nb]     = *(const float4*)(W1 + (size_t)(k0 + k) * 128 + nb);
            *(float4*)&B1s[k * 132 + nb + 4] = *(const float4*)(W1 + (size_t)(k0 + k) * 128 + nb + 4);
        }
        __syncthreads();
        #pragma unroll
        for (int k = 0; k < 16; k++) {
            float4 a = *(const float4*)&As[k * 68 + (ty << 2)];
            unsigned long long ad[4] = { dup2(a.x), dup2(a.y), dup2(a.z), dup2(a.w) };
            const unsigned long long* bp = (const unsigned long long*)&B1s[k * 132 + (tx << 3)];
            unsigned long long b0 = bp[0], b1v = bp[1], b2 = bp[2], b3 = bp[3];
            #pragma unroll
            for (int i = 0; i < 4; i++) {
                fma2(acc1[i][0], ad[i], b0);
                fma2(acc1[i][1], ad[i], b1v);
                fma2(acc1[i][2], ad[i], b2);
                fma2(acc1[i][3], ad[i], b3);
            }
        }
        __syncthreads();
    }
    // write Ht transposed with relu+bias; quad-swizzle rows by tx to spread banks
    #pragma unroll
    for (int jj = 0; jj < 4; jj++) {
        int c = (tx << 3) + 2 * jj;
        int qs = (ty ^ (tx & 7)) << 2;           // swizzled quad base
        #pragma unroll
        for (int i = 0; i < 4; i++) {
            float2 p = unpack2(acc1[i][jj]);
            Ht[(c    ) * 68 + qs + i] = fmaxf(p.x + b1[c], 0.f);
            Ht[(c + 1) * 68 + qs + i] = fmaxf(p.y + b1[c + 1], 0.f);
        }
    }

    // ---- stage 2: M2 = H@W2, acc 4 rows x 4 cols ----
    unsigned long long acc2[4][2];
    #pragma unroll
    for (int i = 0; i < 4; i++) { acc2[i][0] = 0ULL; acc2[i][1] = 0ULL; }
    for (int k0 = 0; k0 < 128; k0 += 16) {
        {   // W2 tile: 16 x 64
            int k = tid >> 4, nb = (tid & 15) << 2;
            *(float4*)&B2s[k * 68 + nb] = *(const float4*)(W2 + (size_t)(k0 + k) * 64 + nb);
        }
        __syncthreads();
        #pragma unroll
        for (int k = 0; k < 16; k++) {
            int k2 = k0 + k;
            float4 a = *(const float4*)&Ht[k2 * 68 + ((ty ^ ((k2 >> 3) & 7)) << 2)];
            unsigned long long ad[4] = { dup2(a.x), dup2(a.y), dup2(a.z), dup2(a.w) };
            const unsigned long long* bp = (const unsigned long long*)&B2s[k * 68 + (tx << 2)];
            unsigned long long b0 = bp[0], b1v = bp[1];
            #pragma unroll
            for (int i = 0; i < 4; i++) {
                fma2(acc2[i][0], ad[i], b0);
                fma2(acc2[i][1], ad[i], b1v);
            }
        }
        __syncthreads();
    }
    #pragma unroll
    for (int i = 0; i < 4; i++) {
        int row = r0 + (ty << 2) + i;
        if (row >= M) continue;
        float2 p0 = unpack2(acc2[i][0]);
        float2 p1 = unpack2(acc2[i][1]);
        __half2 h0 = __floats2half2_rn(p0.x, p0.y);
        __half2 h1 = __floats2half2_rn(p1.x, p1.y);
        *(uint2*)(M2h + (size_t)row * 64 + (tx << 2)) =
            make_uint2(*(unsigned*)&h0, *(unsigned*)&h1);
    }
}

// ---------------- weight transpose [192,64] -> [64,192] ----------------
__global__ void k_transpose(const float* __restrict__ in, float* __restrict__ out) {
    int i = blockIdx.x * blockDim.x + threadIdx.x;
    if (i < EMB * G3) {
        int k = i / G3, g = i - k * G3;
        out[i] = in[g * EMB + k];
    }
}

// ---------------- gi GEMM: gi = zseq @ WTih + bih (fp16 out), 64x192 tile ----------------
__global__ void __launch_bounds__(256) k_gemm_gi(const float* __restrict__ A, const float* __restrict__ bih,
                                                 int M) {
    __shared__ float As[16 * 68];
    __shared__ float Bs[16 * 196];
    int r0 = blockIdx.x * 64;
    int tid = threadIdx.x;
    int ty = tid >> 4, tx = tid & 15;
    unsigned long long acc[4][6];
    #pragma unroll
    for (int i = 0; i < 4; i++)
        #pragma unroll
        for (int jj = 0; jj < 6; jj++) acc[i][jj] = 0ULL;
    for (int k0 = 0; k0 < 64; k0 += 16) {
        {
            int m = tid >> 2, kb = (tid & 3) << 2;
            float4 v = make_float4(0.f, 0.f, 0.f, 0.f);
            if (r0 + m < M) v = *(const float4*)(A + (size_t)(r0 + m) * 64 + k0 + kb);
            As[(kb + 0) * 68 + m] = v.x; As[(kb + 1) * 68 + m] = v.y;
            As[(kb + 2) * 68 + m] = v.z; As[(kb + 3) * 68 + m] = v.w;
        }
        {
            int k = tid >> 4, nb = (tid & 15) * 12;
            const float* bp = g_WTih + (size_t)(k0 + k) * 192 + nb;
            *(float4*)&Bs[k * 196 + nb + 0] = *(const float4*)(bp + 0);
            *(float4*)&Bs[k * 196 + nb + 4] = *(const float4*)(bp + 4);
            *(float4*)&Bs[k * 196 + nb + 8] = *(const float4*)(bp + 8);
        }
        __syncthreads();
        #pragma unroll
        for (int k = 0; k < 16; k++) {
            float4 a = *(const float4*)&As[k * 68 + (ty << 2)];
            unsigned long long ad[4] = { dup2(a.x), dup2(a.y), dup2(a.z), dup2(a.w) };
            const unsigned long long* bp = (const unsigned long long*)&Bs[k * 196 + tx * 12];
            unsigned long long b0 = bp[0], b1 = bp[1], b2 = bp[2];
            unsigned long long b3 = bp[3], b4 = bp[4], b5 = bp[5];
            #pragma unroll
            for (int i = 0; i < 4; i++) {
                fma2(acc[i][0], ad[i], b0);
                fma2(acc[i][1], ad[i], b1);
                fma2(acc[i][2], ad[i], b2);
                fma2(acc[i][3], ad[i], b3);
                fma2(acc[i][4], ad[i], b4);
                fma2(acc[i][5], ad[i], b5);
            }
        }
        __syncthreads();
    }
    #pragma unroll
    for (int i = 0; i < 4; i++) {
        int row = r0 + (ty << 2) + i;
        if (row >= M) continue;
        __half2* op = (__half2*)(g_gih + (size_t)row * 192 + tx * 12);
        #pragma unroll
        for (int jj = 0; jj < 6; jj++) {
            float2 p = unpack2(acc[i][jj]);
            int col = tx * 12 + 2 * jj;
            op[jj] = __floats2half2_rn(p.x + bih[col], p.y + bih[col + 1]);
        }
    }
}

// ---------------- fully fused GRU: all 12 steps; writes z (fp32) + g_hh (fp16) ----------
#define GRU_SMEM_FLOATS (12288 + 64 * 68)
__global__ void __launch_bounds__(256) k_gru_all(const float* __restrict__ bhh,
                                                 float* __restrict__ out, int n) {
    extern __shared__ float S[];
    float* Wh = S;                               // [64][192]
    float* ht = S + 12288;                       // [64 f][68 row]
    int r0 = blockIdx.x * 64;
    int tid = threadIdx.x;
    int ty = tid >> 4, tx = tid & 15;
    for (int i = tid; i < 12288; i += 256) Wh[i] = g_WThh[i];
    for (int i = tid; i < 64 * 68; i += 256) ht[i] = 0.f;
    float bh_r[4], bh_z[4], bh_n[4];
    #pragma unroll
    for (int q = 0; q < 4; q++) {
        bh_r[q] = bhh[(tx << 2) + q];
        bh_z[q] = bhh[64 + (tx << 2) + q];
        bh_n[q] = bhh[128 + (tx << 2) + q];
    }
    __syncthreads();

    for (int t = 0; t < T_STEPS; t++) {
        unsigned long long acc[4][6];
        #pragma unroll
        for (int i = 0; i < 4; i++)
            #pragma unroll
            for (int jj = 0; jj < 6; jj++) acc[i][jj] = 0ULL;
        #pragma unroll 8
        for (int k = 0; k < 64; k++) {
            float4 a = *(const float4*)&ht[k * 68 + (ty << 2)];
            unsigned long long ad[4] = { dup2(a.x), dup2(a.y), dup2(a.z), dup2(a.w) };
            const unsigned long long* br = (const unsigned long long*)&Wh[k * 192 + (tx << 2)];
            const unsigned long long* bz = (const unsigned long long*)&Wh[k * 192 + 64 + (tx << 2)];
            const unsigned long long* bn = (const unsigned long long*)&Wh[k * 192 + 128 + (tx << 2)];
            unsigned long long r0v = br[0], r1v = br[1];
            unsigned long long z0v = bz[0], z1v = bz[1];
            unsigned long long n0v = bn[0], n1v = bn[1];
            #pragma unroll
            for (int i = 0; i < 4; i++) {
                fma2(acc[i][0], ad[i], r0v);
                fma2(acc[i][1], ad[i], r1v);
                fma2(acc[i][2], ad[i], z0v);
                fma2(acc[i][3], ad[i], z1v);
                fma2(acc[i][4], ad[i], n0v);
                fma2(acc[i][5], ad[i], n1v);
            }
        }
        __syncthreads();                         // all ht reads complete
        #pragma unroll
        for (int i = 0; i < 4; i++) {
            int row = (ty << 2) + i;
            int grow = r0 + row;
            if (grow < n) {
                const __half2* gp = (const __half2*)(g_gih + ((size_t)t * n + grow) * 192);
                float2 gr01 = __half22float2(gp[tx * 2]);
                float2 gr23 = __half22float2(gp[tx * 2 + 1]);
                float2 gz01 = __half22float2(gp[32 + tx * 2]);
                float2 gz23 = __half22float2(gp[32 + tx * 2 + 1]);
                float2 gn01 = __half22float2(gp[64 + tx * 2]);
                float2 gn23 = __half22float2(gp[64 + tx * 2 + 1]);
                float grq[4] = { gr01.x, gr01.y, gr23.x, gr23.y };
                float gzq[4] = { gz01.x, gz01.y, gz23.x, gz23.y };
                float gnq[4] = { gn01.x, gn01.y, gn23.x, gn23.y };
                float2 hr01 = unpack2(acc[i][0]), hr23 = unpack2(acc[i][1]);
                float2 hz01 = unpack2(acc[i][2]), hz23 = unpack2(acc[i][3]);
                float2 hn01 = unpack2(acc[i][4]), hn23 = unpack2(acc[i][5]);
                float hrq[4] = { hr01.x, hr01.y, hr23.x, hr23.y };
                float hzq[4] = { hz01.x, hz01.y, hz23.x, hz23.y };
                float hnq[4] = { hn01.x, hn01.y, hn23.x, hn23.y };
                #pragma unroll
                for (int q = 0; q < 4; q++) {
                    int f = (tx << 2) + q;
                    float r  = sigf(grq[q] + hrq[q] + bh_r[q]);
                    float zg = sigf(gzq[q] + hzq[q] + bh_z[q]);
                    float ng = tanhf(gnq[q] + r * (hnq[q] + bh_n[q]));
                    float ho = ht[f * 68 + row];
                    ht[f * 68 + row] = (1.f - zg) * ng + zg * ho;
                }
            }
        }
        __syncthreads();                         // updates visible before next step
    }
    // writeback: z (fp32, at out + n*n) and fp16 copy for decoder
    for (int e = tid; e < 4096; e += 256) {
        int row = e >> 6, f = e & 63;
        int grow = r0 + row;
        if (grow < n) {
            float v = ht[f * 68 + row];
            out[(size_t)n * n + (size_t)grow * 64 + f] = v;
            g_hh[(size_t)grow * 64 + f] = __float2half_rn(v);
        }
    }
}

// ---------------- decoder: softplus(z @ z^T + b), symmetric, HMMA fp16 ----------------
// smem tile: 128 rows x 64 halves, row stride 144 B, 16B-chunk swizzle c' = c ^ (2*(r&3))
__device__ __forceinline__ unsigned sw_ad(int r, int c) {
    return (unsigned)(r * 144 + (((c ^ ((r & 3) << 1)) & 7) << 4));
}

__global__ void __launch_bounds__(256) k_decode_mma(float* __restrict__ C,
                                                    const float* __restrict__ dbias, int n) {
    int bj = blockIdx.x, bi = blockIdx.y;
    if (bj < bi) return;
    __shared__ __align__(16) unsigned char Asm[128 * 144];
    __shared__ __align__(16) unsigned char Bsm[128 * 144];
    int tid = threadIdx.x;
    int i0 = bi * 128, j0 = bj * 128;
    for (int idx = tid; idx < 1024; idx += 256) {
        int r = idx >> 3, c = idx & 7;
        uint4 va = make_uint4(0u, 0u, 0u, 0u), vb = va;
        if (i0 + r < n) va = *(const uint4*)(g_hh + (size_t)(i0 + r) * 64 + c * 8);
        if (j0 + r < n) vb = *(const uint4*)(g_hh + (size_t)(j0 + r) * 64 + c * 8);
        *(uint4*)(Asm + sw_ad(r, c)) = va;
        *(uint4*)(Bsm + sw_ad(r, c)) = vb;
    }
    __syncthreads();
    int wid = tid >> 5, lane = tid & 31;
    int lr = lane >> 2, lm = lane & 3;
    int R  = (wid >> 1) << 5;                    // warp m base (0,32,64,96)
    int Jb = (wid & 1) << 6;                     // warp n base (0,64)
    float d[2][8][4];
    #pragma unroll
    for (int mi = 0; mi < 2; mi++)
        #pragma unroll
        for (int ni = 0; ni < 8; ni++)
            #pragma unroll
            for (int q = 0; q < 4; q++) d[mi][ni][q] = 0.f;

    #pragma unroll
    for (int ks = 0; ks < 4; ks++) {
        unsigned a[2][4];
        #pragma unroll
        for (int mi = 0; mi < 2; mi++) {
            int r_ = R + (mi << 4) + lr;
            a[mi][0] = *(const unsigned*)(Asm + sw_ad(r_,     2 * ks)     + (lm << 2));
            a[mi][1] = *(const unsigned*)(Asm + sw_ad(r_ + 8, 2 * ks)     + (lm << 2));
            a[mi][2] = *(const unsigned*)(Asm + sw_ad(r_,     2 * ks + 1) + (lm << 2));
            a[mi][3] = *(const unsigned*)(Asm + sw_ad(r_ + 8, 2 * ks + 1) + (lm << 2));
        }
        #pragma unroll
        for (int ni = 0; ni < 8; ni++) {
            int jr = Jb + (ni << 3) + lr;
            unsigned b0 = *(const unsigned*)(Bsm + sw_ad(jr, 2 * ks)     + (lm << 2));
            unsigned b1 = *(const unsigned*)(Bsm + sw_ad(jr, 2 * ks + 1) + (lm << 2));
            #pragma unroll
            for (int mi = 0; mi < 2; mi++) {
                asm volatile("mma.sync.aligned.m16n8k16.row.col.f32.f16.f16.f32 "
                    "{%0,%1,%2,%3}, {%4,%5,%6,%7}, {%8,%9}, {%0,%1,%2,%3};"
                    : "+f"(d[mi][ni][0]), "+f"(d[mi][ni][1]),
                      "+f"(d[mi][ni][2]), "+f"(d[mi][ni][3])
                    : "r"(a[mi][0]), "r"(a[mi][1]), "r"(a[mi][2]), "r"(a[mi][3]),
                      "r"(b0), "r"(b1));
            }
        }
    }
    float db = dbias[0];
    #pragma unroll
    for (int mi = 0; mi < 2; mi++)
        #pragma unroll
        for (int ni = 0; ni < 8; ni++) {
            int gi0 = i0 + R + (mi << 4) + lr;
            int gj0 = j0 + Jb + (ni << 3) + (lm << 1);
            float v0 = softplusf(d[mi][ni][0] + db);
            float v1 = softplusf(d[mi][ni][1] + db);
            float v2 = softplusf(d[mi][ni][2] + db);
            float v3 = softplusf(d[mi][ni][3] + db);
            if (gi0 < n) {
                if (gj0 + 1 < n)      *(float2*)(C + (size_t)gi0 * n + gj0) = make_float2(v0, v1);
                else if (gj0 < n)     C[(size_t)gi0 * n + gj0] = v0;
            }
            if (gi0 + 8 < n) {
                if (gj0 + 1 < n)      *(float2*)(C + (size_t)(gi0 + 8) * n + gj0) = make_float2(v2, v3);
                else if (gj0 < n)     C[(size_t)(gi0 + 8) * n + gj0] = v2;
            }
            if (bi != bj) {          // mirror C[j][i] = C[i][j]
                if (gj0 < n) {
                    if (gi0 < n)     C[(size_t)gj0 * n + gi0]     = v0;
                    if (gi0 + 8 < n) C[(size_t)gj0 * n + gi0 + 8] = v2;
                }
                if (gj0 + 1 < n) {
                    if (gi0 < n)     C[(size_t)(gj0 + 1) * n + gi0]     = v1;
                    if (gi0 + 8 < n) C[(size_t)(gj0 + 1) * n + gi0 + 8] = v3;
                }
            }
        }
}

// ---------------- host ----------------
extern "C" void kernel_launch(void* const* d_in, const int* in_sizes, int n_in,
                              void* d_out, int out_size) {
    const float* x     = (const float*)d_in[0];
    const int*   ei    = (const int*)d_in[1];      // int32! (JAX demotes int64)
    const float* ew    = (const float*)d_in[2];
    const float* W1    = (const float*)d_in[3];
    const float* b1    = (const float*)d_in[4];
    const float* W2    = (const float*)d_in[5];
    const float* b2    = (const float*)d_in[6];
    const float* Wih   = (const float*)d_in[7];
    const float* Whh   = (const float*)d_in[8];
    const float* bih   = (const float*)d_in[9];
    const float* bhh   = (const float*)d_in[10];
    const float* dbias = (const float*)d_in[11];
    float* out = (float*)d_out;

    int E = in_sizes[2];
    int N = in_sizes[0] / (T_STEPS * IN_DIM);
    if (N > NMAX) N = NMAX;                        // hard guard: never OOB scratch
    if (E > EDGEMAX - N) E = EDGEMAX - N;
    int M = T_STEPS * N;

    float  *p_xagg, *p_zseq, *p_WTih, *p_WThh;
    __half *p_xh, *p_M2h;
    cudaGetSymbolAddress((void**)&p_xh,   g_xh);
    cudaGetSymbolAddress((void**)&p_xagg, g_xagg);
    cudaGetSymbolAddress((void**)&p_M2h,  g_M2h);
    cudaGetSymbolAddress((void**)&p_zseq, g_zseq);
    cudaGetSymbolAddress((void**)&p_WTih, g_WTih);
    cudaGetSymbolAddress((void**)&p_WThh, g_WThh);

    static int smem_set = 0;
    if (!smem_set) {
        cudaFuncSetAttribute(k_gru_all, cudaFuncAttributeMaxDynamicSharedMemorySize,
                             GRU_SMEM_FLOATS * (int)sizeof(float));
        smem_set = 1;
    }

    const int B = 256;
    // graph preprocessing
    k_init  <<<(N + B - 1) / B, B>>>(N);
    k_degcnt<<<(E + B - 1) / B, B>>>(ei, ew, E, N);
    k_dinv  <<<(N + B - 1) / B, B>>>(N);
    k_scan  <<<1, 1024>>>(N);
    k_fill  <<<(E + N + B - 1) / B, B>>>(ei, ew, E, N);

    // encoder: AX -> fused (relu(.W1+b1)).W2 -> fp16 -> A(.)+b2
    dim3 aggGrid((N * 32 + B - 1) / B, T_STEPS);
    k_tohalf<<<(M * 32 + B - 1) / B, B>>>(x, p_xh, M * 32);
    k_agg_h <<<aggGrid, B>>>((const __half2*)p_xh, p_xagg, nullptr, N);
    k_enc   <<<(M + 63) / 64, B>>>(p_xagg, W1, b1, W2, p_M2h, M);
    k_agg_h <<<aggGrid, B>>>((const __half2*)p_M2h, p_zseq, b2, N);

    // GRU
    k_transpose<<<(EMB * G3 + B - 1) / B, B>>>(Wih, p_WTih);
    k_transpose<<<(EMB * G3 + B - 1) / B, B>>>(Whh, p_WThh);
    k_gemm_gi<<<(M + 63) / 64, B>>>(p_zseq, bih, M);
    k_gru_all<<<(N + 63) / 64, B, GRU_SMEM_FLOATS * sizeof(float)>>>(bhh, out, N);

    // decoder (also covers z already written by k_gru_all)
    int gb = (N + 127) / 128;
    k_decode_mma<<<dim3(gb, gb), B>>>(out, dbias, N);
}

// round 10
// speedup vs baseline: 2.4592x; 1.2801x over previous
#include <cuda_runtime.h>
#include <cuda_fp16.h>
#include <cstdint>

#define T_STEPS 12
#define IN_DIM  64
#define HID_DIM 128
#define EMB     64
#define G3      192

#define NMAX    10240
#define EDGEMAX 360448   /* > E + N */

// ---------------- scratch (static __device__, no allocations) ----------------
__device__ float  g_deg [NMAX];
__device__ float  g_dinv[NMAX];
__device__ int    g_cnt [NMAX];
__device__ int    g_off [NMAX + 1];
__device__ int    g_cur [NMAX];
__device__ int2   g_ce  [EDGEMAX];                      // (row, norm-as-int)
__device__ __half g_xh  [(size_t)T_STEPS * NMAX * IN_DIM];
__device__ __half g_xaggh[(size_t)T_STEPS * NMAX * IN_DIM];
__device__ __half g_M2h [(size_t)T_STEPS * NMAX * EMB];
__device__ __half g_zseqh[(size_t)T_STEPS * NMAX * EMB];
__device__ __half g_gih [(size_t)T_STEPS * NMAX * G3];
__device__ __half g_hh  [(size_t)NMAX * EMB];
__device__ float  g_WThh[EMB * G3];
__device__ __half g_W1t [HID_DIM * IN_DIM];             // [n=128][k=64]
__device__ __half g_W2t [EMB * HID_DIM];                // [n=64][k=128]
__device__ __half g_Wihh[G3 * EMB];                     // [n=192][k=64] (= torch layout)

// ---------------- small helpers ----------------
__device__ __forceinline__ float sigf(float x) { return 1.f / (1.f + __expf(-x)); }

__device__ __forceinline__ float softplusf(float x) {
    float u = __expf(-fabsf(x));                 // = exp(x) when x<0
    float r = fmaxf(x, 0.f) + __logf(1.f + u);
    if (x < -15.f) r = u;                        // avoid 1+u==1 rounding
    return r;
}

__device__ __forceinline__ unsigned long long dup2(float a) {
    unsigned long long r;
    asm("mov.b64 %0, {%1, %1};" : "=l"(r) : "f"(a));
    return r;
}
__device__ __forceinline__ float2 unpack2(unsigned long long v) {
    float lo, hi;
    asm("mov.b64 {%0, %1}, %2;" : "=f"(lo), "=f"(hi) : "l"(v));
    return make_float2(lo, hi);
}
__device__ __forceinline__ void fma2(unsigned long long& d, unsigned long long a, unsigned long long b) {
    asm("fma.rn.f32x2 %0, %1, %2, %0;" : "+l"(d) : "l"(a), "l"(b));
}
__device__ __forceinline__ void mma16816(float* d, unsigned a0, unsigned a1, unsigned a2, unsigned a3,
                                         unsigned b0, unsigned b1) {
    asm volatile("mma.sync.aligned.m16n8k16.row.col.f32.f16.f16.f32 "
        "{%0,%1,%2,%3}, {%4,%5,%6,%7}, {%8,%9}, {%0,%1,%2,%3};"
        : "+f"(d[0]), "+f"(d[1]), "+f"(d[2]), "+f"(d[3])
        : "r"(a0), "r"(a1), "r"(a2), "r"(a3), "r"(b0), "r"(b1));
}

// ---------------- graph preprocessing ----------------
__global__ void k_init(int n) {
    int i = blockIdx.x * blockDim.x + threadIdx.x;
    if (i < n) { g_deg[i] = 1.f; g_cnt[i] = 1; }   // self-loop weight/count
}

// edge_index is INT32 (JAX without x64 demotes int64 -> int32): layout [2, E]
__global__ void k_degcnt(const int* __restrict__ ei, const float* __restrict__ ew, int E, int n) {
    int e = blockIdx.x * blockDim.x + threadIdx.x;
    if (e < E) {
        int c = ei[E + e];
        c = min(max(c, 0), n - 1);               // defensive clamp
        atomicAdd(&g_deg[c], ew[e]);
        atomicAdd(&g_cnt[c], 1);
    }
}

__global__ void k_dinv(int n) {
    int i = blockIdx.x * blockDim.x + threadIdx.x;
    if (i < n) {
        float d = g_deg[i];
        g_dinv[i] = (d > 0.f) ? rsqrtf(d) : 0.f;
    }
}

__global__ void k_scan(int n) {      // <<<1, 1024>>>
    __shared__ int sums[1024];
    int tid = threadIdx.x;
    int per = (n + 1023) / 1024;
    int start = tid * per;
    int end   = min(start + per, n);
    int s = 0;
    for (int i = start; i < end; i++) s += g_cnt[i];
    sums[tid] = s;
    __syncthreads();
    for (int d = 1; d < 1024; d <<= 1) {
        int v = 0;
        if (tid >= d) v = sums[tid - d];
        __syncthreads();
        if (tid >= d) sums[tid] += v;
        __syncthreads();
    }
    int base = (tid == 0) ? 0 : sums[tid - 1];
    for (int i = start; i < end; i++) {
        g_off[i] = base; g_cur[i] = base;
        base += g_cnt[i];
    }
    if (tid == 1023) g_off[n] = sums[1023];
}

__global__ void k_fill(const int* __restrict__ ei, const float* __restrict__ ew, int E, int n) {
    int e = blockIdx.x * blockDim.x + threadIdx.x;
    int total = E + n;
    if (e >= total) return;
    int r, c; float w;
    if (e < E) {
        r = ei[e]; c = ei[E + e]; w = ew[e];
        r = min(max(r, 0), n - 1);
        c = min(max(c, 0), n - 1);
    }
    else       { r = c = e - E; w = 1.f; }
    float norm = g_dinv[r] * w * g_dinv[c];
    int pos = atomicAdd(&g_cur[c], 1);
    pos = min(max(pos, 0), EDGEMAX - 1);         // defensive clamp
    g_ce[pos] = make_int2(r, __float_as_int(norm));
}

// ---------------- float -> half conversion (paired) ----------------
__global__ void k_tohalf(const float* __restrict__ src, __half* __restrict__ dst, int cnt2) {
    int i = blockIdx.x * blockDim.x + threadIdx.x;
    if (i < cnt2) {
        float2 v = ((const float2*)src)[i];
        ((__half2*)dst)[i] = __float22half2_rn(v);
    }
}

// ---------------- weight prep: W1t/W2t (transposed) + Wih, all fp16 ----------------
__global__ void k_convw(const float* __restrict__ W1, const float* __restrict__ W2,
                        const float* __restrict__ Wih) {
    int i = blockIdx.x * blockDim.x + threadIdx.x;
    if (i < 8192) {                              // W1t[n][k] = W1[k][n], n<128,k<64
        int n = i >> 6, k = i & 63;
        g_W1t[i] = __float2half_rn(W1[k * 128 + n]);
    } else if (i < 16384) {                      // W2t[n][k] = W2[k][n], n<64,k<128
        int j = i - 8192;
        int n = j >> 7, k = j & 127;
        g_W2t[j] = __float2half_rn(W2[k * 64 + n]);
    } else if (i < 28672) {                      // Wih direct ([192][64] already [n][k])
        int j = i - 16384;
        g_Wihh[j] = __float2half_rn(Wih[j]);
    }
}

// ---------------- weight transpose [192,64] -> [64,192] (fp32, for GRU) ----------------
__global__ void k_transpose(const float* __restrict__ in, float* __restrict__ out) {
    int i = blockIdx.x * blockDim.x + threadIdx.x;
    if (i < EMB * G3) {
        int k = i / G3, g = i - k * G3;
        out[i] = in[g * EMB + k];
    }
}

// ---------------- aggregation (fp16 gather, fp32 accumulate, fp16 out), warp/node ----
__global__ void k_agg_h(const __half2* __restrict__ in, __half2* __restrict__ out,
                        const float* __restrict__ bias, int n) {
    int nd   = (blockIdx.x * blockDim.x + threadIdx.x) >> 5;
    int lane = threadIdx.x & 31;
    int t    = blockIdx.y;
    if (nd >= n) return;
    int s = g_off[nd], e = g_off[nd + 1];
    const __half2* base = in + (size_t)t * n * 32;
    float a0 = 0.f, a1 = 0.f;
    int j = s;
    for (; j + 3 < e; j += 4) {                  // 4-way unroll for MLP
        int2 p0 = g_ce[j], p1 = g_ce[j + 1], p2 = g_ce[j + 2], p3 = g_ce[j + 3];
        float2 v0 = __half22float2(base[(size_t)p0.x * 32 + lane]);
        float2 v1 = __half22float2(base[(size_t)p1.x * 32 + lane]);
        float2 v2 = __half22float2(base[(size_t)p2.x * 32 + lane]);
        float2 v3 = __half22float2(base[(size_t)p3.x * 32 + lane]);
        float w0 = __int_as_float(p0.y), w1 = __int_as_float(p1.y);
        float w2 = __int_as_float(p2.y), w3 = __int_as_float(p3.y);
        a0 = fmaf(w0, v0.x, a0); a1 = fmaf(w0, v0.y, a1);
        a0 = fmaf(w1, v1.x, a0); a1 = fmaf(w1, v1.y, a1);
        a0 = fmaf(w2, v2.x, a0); a1 = fmaf(w2, v2.y, a1);
        a0 = fmaf(w3, v3.x, a0); a1 = fmaf(w3, v3.y, a1);
    }
    for (; j < e; j++) {
        int2 p0 = g_ce[j];
        float2 v0 = __half22float2(base[(size_t)p0.x * 32 + lane]);
        float w0 = __int_as_float(p0.y);
        a0 = fmaf(w0, v0.x, a0); a1 = fmaf(w0, v0.y, a1);
    }
    if (bias) { a0 += bias[lane * 2]; a1 += bias[lane * 2 + 1]; }
    out[((size_t)t * n + nd) * 32 + lane] = __floats2half2_rn(a0, a1);
}

// ---------------- fused encoder on HMMA: M2 = relu(xagg@W1+b1)@W2 (all fp16 ops) -------
// smem: [0,18432) Ax[128][144B] (reused for W2t[64][272B]); [18432,36864) W1t[128][144B];
//       [36864,71680) Hs[128][272B]
#define ENC_SMEM_BYTES 71680
__global__ void __launch_bounds__(256) k_enc_mma(const float* __restrict__ b1,
                                                 __half* __restrict__ M2h, int M) {
    extern __shared__ __align__(16) unsigned char ES[];
    unsigned char* Ax  = ES;
    unsigned char* W2t = ES;
    unsigned char* W1t = ES + 18432;
    unsigned char* Hs  = ES + 36864;
    int r0 = blockIdx.x * 128;
    int tid = threadIdx.x;
    for (int idx = tid; idx < 1024; idx += 256) {
        int r = idx >> 3, c = idx & 7;
        uint4 v = make_uint4(0u, 0u, 0u, 0u);
        if (r0 + r < M) v = *(const uint4*)(g_xaggh + (size_t)(r0 + r) * 64 + c * 8);
        *(uint4*)(Ax + r * 144 + c * 16) = v;
        *(uint4*)(W1t + r * 144 + c * 16) = *(const uint4*)(g_W1t + r * 64 + c * 8);
    }
    __syncthreads();
    int wid = tid >> 5, lane = tid & 31, lr = lane >> 2, lm = lane & 3;
    int mb = wid << 4;
    float d1[16][4];
    #pragma unroll
    for (int ni = 0; ni < 16; ni++)
        #pragma unroll
        for (int q = 0; q < 4; q++) d1[ni][q] = 0.f;
    #pragma unroll
    for (int ks = 0; ks < 4; ks++) {
        int ra = mb + lr;
        unsigned a0 = *(const unsigned*)(Ax + ra * 144       + ks * 32      + lm * 4);
        unsigned a1 = *(const unsigned*)(Ax + (ra + 8) * 144 + ks * 32      + lm * 4);
        unsigned a2 = *(const unsigned*)(Ax + ra * 144       + ks * 32 + 16 + lm * 4);
        unsigned a3 = *(const unsigned*)(Ax + (ra + 8) * 144 + ks * 32 + 16 + lm * 4);
        #pragma unroll
        for (int ni = 0; ni < 16; ni++) {
            int rb = ni * 8 + lr;
            unsigned b0 = *(const unsigned*)(W1t + rb * 144 + ks * 32      + lm * 4);
            unsigned b1v = *(const unsigned*)(W1t + rb * 144 + ks * 32 + 16 + lm * 4);
            mma16816(d1[ni], a0, a1, a2, a3, b0, b1v);
        }
    }
    __syncthreads();                             // Ax reads done -> buffer reusable
    #pragma unroll
    for (int ni = 0; ni < 16; ni++) {            // relu+bias -> Hs (fp16)
        int col = ni * 8 + lm * 2;
        float bb0 = b1[col], bb1 = b1[col + 1];
        __half2 h01 = __floats2half2_rn(fmaxf(d1[ni][0] + bb0, 0.f), fmaxf(d1[ni][1] + bb1, 0.f));
        __half2 h23 = __floats2half2_rn(fmaxf(d1[ni][2] + bb0, 0.f), fmaxf(d1[ni][3] + bb1, 0.f));
        *(unsigned*)(Hs + (mb + lr) * 272     + col * 2) = *(unsigned*)&h01;
        *(unsigned*)(Hs + (mb + lr + 8) * 272 + col * 2) = *(unsigned*)&h23;
    }
    for (int idx = tid; idx < 1024; idx += 256) { // W2t: 64 rows x 16 chunks
        int r = idx >> 4, c = idx & 15;
        *(uint4*)(W2t + r * 272 + c * 16) = *(const uint4*)(g_W2t + r * 128 + c * 8);
    }
    __syncthreads();
    float d2[8][4];
    #pragma unroll
    for (int ni = 0; ni < 8; ni++)
        #pragma unroll
        for (int q = 0; q < 4; q++) d2[ni][q] = 0.f;
    #pragma unroll
    for (int ks = 0; ks < 8; ks++) {
        int ra = mb + lr;
        unsigned a0 = *(const unsigned*)(Hs + ra * 272       + ks * 32      + lm * 4);
        unsigned a1 = *(const unsigned*)(Hs + (ra + 8) * 272 + ks * 32      + lm * 4);
        unsigned a2 = *(const unsigned*)(Hs + ra * 272       + ks * 32 + 16 + lm * 4);
        unsigned a3 = *(const unsigned*)(Hs + (ra + 8) * 272 + ks * 32 + 16 + lm * 4);
        #pragma unroll
        for (int ni = 0; ni < 8; ni++) {
            int rb = ni * 8 + lr;
            unsigned b0 = *(const unsigned*)(W2t + rb * 272 + ks * 32      + lm * 4);
            unsigned b1v = *(const unsigned*)(W2t + rb * 272 + ks * 32 + 16 + lm * 4);
            mma16816(d2[ni], a0, a1, a2, a3, b0, b1v);
        }
    }
    #pragma unroll
    for (int ni = 0; ni < 8; ni++) {
        int col = ni * 8 + lm * 2;
        int row = r0 + mb + lr;
        if (row < M) {
            __half2 h = __floats2half2_rn(d2[ni][0], d2[ni][1]);
            *(unsigned*)(M2h + (size_t)row * 64 + col) = *(unsigned*)&h;
        }
        if (row + 8 < M) {
            __half2 h = __floats2half2_rn(d2[ni][2], d2[ni][3]);
            *(unsigned*)(M2h + (size_t)(row + 8) * 64 + col) = *(unsigned*)&h;
        }
    }
}

// ---------------- gi GEMM on HMMA: gi = zseq @ Wih^T + bih (fp16 out) ----------------
__global__ void __launch_bounds__(256) k_gi_mma(const float* __restrict__ bih, int M) {
    __shared__ __align__(16) unsigned char Az[128 * 144];
    __shared__ __align__(16) unsigned char Wm[192 * 144];
    int r0 = blockIdx.x * 128;
    int tid = threadIdx.x;
    for (int idx = tid; idx < 1024; idx += 256) {
        int r = idx >> 3, c = idx & 7;
        uint4 v = make_uint4(0u, 0u, 0u, 0u);
        if (r0 + r < M) v = *(const uint4*)(g_zseqh + (size_t)(r0 + r) * 64 + c * 8);
        *(uint4*)(Az + r * 144 + c * 16) = v;
    }
    for (int idx = tid; idx < 1536; idx += 256) {
        int r = idx >> 3, c = idx & 7;
        *(uint4*)(Wm + r * 144 + c * 16) = *(const uint4*)(g_Wihh + r * 64 + c * 8);
    }
    __syncthreads();
    int wid = tid >> 5, lane = tid & 31, lr = lane >> 2, lm = lane & 3;
    int mb = wid << 4;
    float d[24][4];
    #pragma unroll
    for (int ni = 0; ni < 24; ni++)
        #pragma unroll
        for (int q = 0; q < 4; q++) d[ni][q] = 0.f;
    #pragma unroll
    for (int ks = 0; ks < 4; ks++) {
        int ra = mb + lr;
        unsigned a0 = *(const unsigned*)(Az + ra * 144       + ks * 32      + lm * 4);
        unsigned a1 = *(const unsigned*)(Az + (ra + 8) * 144 + ks * 32      + lm * 4);
        unsigned a2 = *(const unsigned*)(Az + ra * 144       + ks * 32 + 16 + lm * 4);
        unsigned a3 = *(const unsigned*)(Az + (ra + 8) * 144 + ks * 32 + 16 + lm * 4);
        #pragma unroll
        for (int ni = 0; ni < 24; ni++) {
            int rb = ni * 8 + lr;
            unsigned b0 = *(const unsigned*)(Wm + rb * 144 + ks * 32      + lm * 4);
            unsigned b1v = *(const unsigned*)(Wm + rb * 144 + ks * 32 + 16 + lm * 4);
            mma16816(d[ni], a0, a1, a2, a3, b0, b1v);
        }
    }
    #pragma unroll
    for (int ni = 0; ni < 24; ni++) {
        int col = ni * 8 + lm * 2;
        float bb0 = bih[col], bb1 = bih[col + 1];
        int row = r0 + mb + lr;
        if (row < M) {
            __half2 h = __floats2half2_rn(d[ni][0] + bb0, d[ni][1] + bb1);
            *(unsigned*)(g_gih + (size_t)row * 192 + col) = *(unsigned*)&h;
        }
        if (row + 8 < M) {
            __half2 h = __floats2half2_rn(d[ni][2] + bb0, d[ni][3] + bb1);
            *(unsigned*)(g_gih + (size_t)(row + 8) * 192 + col) = *(unsigned*)&h;
        }
    }
}

// ---------------- fully fused GRU: all 12 steps; writes z (fp32) + g_hh (fp16) ----------
#define GRU_SMEM_FLOATS (12288 + 64 * 68)
__global__ void __launch_bounds__(256) k_gru_all(const float* __restrict__ bhh,
                                                 float* __restrict__ out, int n) {
    extern __shared__ float S[];
    float* Wh = S;                               // [64][192]
    float* ht = S + 12288;                       // [64 f][68 row]
    int r0 = blockIdx.x * 64;
    int tid = threadIdx.x;
    int ty = tid >> 4, tx = tid & 15;
    for (int i = tid; i < 12288; i += 256) Wh[i] = g_WThh[i];
    for (int i = tid; i < 64 * 68; i += 256) ht[i] = 0.f;
    float bh_r[4], bh_z[4], bh_n[4];
    #pragma unroll
    for (int q = 0; q < 4; q++) {
        bh_r[q] = bhh[(tx << 2) + q];
        bh_z[q] = bhh[64 + (tx << 2) + q];
        bh_n[q] = bhh[128 + (tx << 2) + q];
    }
    __syncthreads();

    for (int t = 0; t < T_STEPS; t++) {
        unsigned long long acc[4][6];
        #pragma unroll
        for (int i = 0; i < 4; i++)
            #pragma unroll
            for (int jj = 0; jj < 6; jj++) acc[i][jj] = 0ULL;
        #pragma unroll 8
        for (int k = 0; k < 64; k++) {
            float4 a = *(const float4*)&ht[k * 68 + (ty << 2)];
            unsigned long long ad[4] = { dup2(a.x), dup2(a.y), dup2(a.z), dup2(a.w) };
            const unsigned long long* br = (const unsigned long long*)&Wh[k * 192 + (tx << 2)];
            const unsigned long long* bz = (const unsigned long long*)&Wh[k * 192 + 64 + (tx << 2)];
            const unsigned long long* bn = (const unsigned long long*)&Wh[k * 192 + 128 + (tx << 2)];
            unsigned long long r0v = br[0], r1v = br[1];
            unsigned long long z0v = bz[0], z1v = bz[1];
            unsigned long long n0v = bn[0], n1v = bn[1];
            #pragma unroll
            for (int i = 0; i < 4; i++) {
                fma2(acc[i][0], ad[i], r0v);
                fma2(acc[i][1], ad[i], r1v);
                fma2(acc[i][2], ad[i], z0v);
                fma2(acc[i][3], ad[i], z1v);
                fma2(acc[i][4], ad[i], n0v);
                fma2(acc[i][5], ad[i], n1v);
            }
        }
        __syncthreads();                         // all ht reads complete
        #pragma unroll
        for (int i = 0; i < 4; i++) {
            int row = (ty << 2) + i;
            int grow = r0 + row;
            if (grow < n) {
                const __half2* gp = (const __half2*)(g_gih + ((size_t)t * n + grow) * 192);
                float2 gr01 = __half22float2(gp[tx * 2]);
                float2 gr23 = __half22float2(gp[tx * 2 + 1]);
                float2 gz01 = __half22float2(gp[32 + tx * 2]);
                float2 gz23 = __half22float2(gp[32 + tx * 2 + 1]);
                float2 gn01 = __half22float2(gp[64 + tx * 2]);
                float2 gn23 = __half22float2(gp[64 + tx * 2 + 1]);
                float grq[4] = { gr01.x, gr01.y, gr23.x, gr23.y };
                float gzq[4] = { gz01.x, gz01.y, gz23.x, gz23.y };
                float gnq[4] = { gn01.x, gn01.y, gn23.x, gn23.y };
                float2 hr01 = unpack2(acc[i][0]), hr23 = unpack2(acc[i][1]);
                float2 hz01 = unpack2(acc[i][2]), hz23 = unpack2(acc[i][3]);
                float2 hn01 = unpack2(acc[i][4]), hn23 = unpack2(acc[i][5]);
                float hrq[4] = { hr01.x, hr01.y, hr23.x, hr23.y };
                float hzq[4] = { hz01.x, hz01.y, hz23.x, hz23.y };
                float hnq[4] = { hn01.x, hn01.y, hn23.x, hn23.y };
                #pragma unroll
                for (int q = 0; q < 4; q++) {
                    int f = (tx << 2) + q;
                    float r  = sigf(grq[q] + hrq[q] + bh_r[q]);
                    float zg = sigf(gzq[q] + hzq[q] + bh_z[q]);
                    float ng = tanhf(gnq[q] + r * (hnq[q] + bh_n[q]));
                    float ho = ht[f * 68 + row];
                    ht[f * 68 + row] = (1.f - zg) * ng + zg * ho;
                }
            }
        }
        __syncthreads();                         // updates visible before next step
    }
    // writeback: z (fp32, at out + n*n) and fp16 copy for decoder
    for (int e = tid; e < 4096; e += 256) {
        int row = e >> 6, f = e & 63;
        int grow = r0 + row;
        if (grow < n) {
            float v = ht[f * 68 + row];
            out[(size_t)n * n + (size_t)grow * 64 + f] = v;
            g_hh[(size_t)grow * 64 + f] = __float2half_rn(v);
        }
    }
}

// ---------------- decoder: softplus(z @ z^T + b), symmetric, HMMA fp16 ----------------
// smem tile: 128 rows x 64 halves, row stride 144 B, 16B-chunk swizzle c' = c ^ (2*(r&3))
__device__ __forceinline__ unsigned sw_ad(int r, int c) {
    return (unsigned)(r * 144 + (((c ^ ((r & 3) << 1)) & 7) << 4));
}

__global__ void __launch_bounds__(256) k_decode_mma(float* __restrict__ C,
                                                    const float* __restrict__ dbias, int n) {
    int bj = blockIdx.x, bi = blockIdx.y;
    if (bj < bi) return;
    __shared__ __align__(16) unsigned char Asm[128 * 144];
    __shared__ __align__(16) unsigned char Bsm[128 * 144];
    int tid = threadIdx.x;
    int i0 = bi * 128, j0 = bj * 128;
    for (int idx = tid; idx < 1024; idx += 256) {
        int r = idx >> 3, c = idx & 7;
        uint4 va = make_uint4(0u, 0u, 0u, 0u), vb = va;
        if (i0 + r < n) va = *(const uint4*)(g_hh + (size_t)(i0 + r) * 64 + c * 8);
        if (j0 + r < n) vb = *(const uint4*)(g_hh + (size_t)(j0 + r) * 64 + c * 8);
        *(uint4*)(Asm + sw_ad(r, c)) = va;
        *(uint4*)(Bsm + sw_ad(r, c)) = vb;
    }
    __syncthreads();
    int wid = tid >> 5, lane = tid & 31;
    int lr = lane >> 2, lm = lane & 3;
    int R  = (wid >> 1) << 5;                    // warp m base (0,32,64,96)
    int Jb = (wid & 1) << 6;                     // warp n base (0,64)
    float d[2][8][4];
    #pragma unroll
    for (int mi = 0; mi < 2; mi++)
        #pragma unroll
        for (int ni = 0; ni < 8; ni++)
            #pragma unroll
            for (int q = 0; q < 4; q++) d[mi][ni][q] = 0.f;

    #pragma unroll
    for (int ks = 0; ks < 4; ks++) {
        unsigned a[2][4];
        #pragma unroll
        for (int mi = 0; mi < 2; mi++) {
            int r_ = R + (mi << 4) + lr;
            a[mi][0] = *(const unsigned*)(Asm + sw_ad(r_,     2 * ks)     + (lm << 2));
            a[mi][1] = *(const unsigned*)(Asm + sw_ad(r_ + 8, 2 * ks)     + (lm << 2));
            a[mi][2] = *(const unsigned*)(Asm + sw_ad(r_,     2 * ks + 1) + (lm << 2));
            a[mi][3] = *(const unsigned*)(Asm + sw_ad(r_ + 8, 2 * ks + 1) + (lm << 2));
        }
        #pragma unroll
        for (int ni = 0; ni < 8; ni++) {
            int jr = Jb + (ni << 3) + lr;
            unsigned b0 = *(const unsigned*)(Bsm + sw_ad(jr, 2 * ks)     + (lm << 2));
            unsigned b1 = *(const unsigned*)(Bsm + sw_ad(jr, 2 * ks + 1) + (lm << 2));
            #pragma unroll
            for (int mi = 0; mi < 2; mi++) {
                asm volatile("mma.sync.aligned.m16n8k16.row.col.f32.f16.f16.f32 "
                    "{%0,%1,%2,%3}, {%4,%5,%6,%7}, {%8,%9}, {%0,%1,%2,%3};"
                    : "+f"(d[mi][ni][0]), "+f"(d[mi][ni][1]),
                      "+f"(d[mi][ni][2]), "+f"(d[mi][ni][3])
                    : "r"(a[mi][0]), "r"(a[mi][1]), "r"(a[mi][2]), "r"(a[mi][3]),
                      "r"(b0), "r"(b1));
            }
        }
    }
    float db = dbias[0];
    #pragma unroll
    for (int mi = 0; mi < 2; mi++)
        #pragma unroll
        for (int ni = 0; ni < 8; ni++) {
            int gi0 = i0 + R + (mi << 4) + lr;
            int gj0 = j0 + Jb + (ni << 3) + (lm << 1);
            float v0 = softplusf(d[mi][ni][0] + db);
            float v1 = softplusf(d[mi][ni][1] + db);
            float v2 = softplusf(d[mi][ni][2] + db);
            float v3 = softplusf(d[mi][ni][3] + db);
            if (gi0 < n) {
                if (gj0 + 1 < n)      *(float2*)(C + (size_t)gi0 * n + gj0) = make_float2(v0, v1);
                else if (gj0 < n)     C[(size_t)gi0 * n + gj0] = v0;
            }
            if (gi0 + 8 < n) {
                if (gj0 + 1 < n)      *(float2*)(C + (size_t)(gi0 + 8) * n + gj0) = make_float2(v2, v3);
                else if (gj0 < n)     C[(size_t)(gi0 + 8) * n + gj0] = v2;
            }
            if (bi != bj) {          // mirror C[j][i] = C[i][j]
                if (gj0 < n) {
                    if (gi0 < n)     C[(size_t)gj0 * n + gi0]     = v0;
                    if (gi0 + 8 < n) C[(size_t)gj0 * n + gi0 + 8] = v2;
                }
                if (gj0 + 1 < n) {
                    if (gi0 < n)     C[(size_t)(gj0 + 1) * n + gi0]     = v1;
                    if (gi0 + 8 < n) C[(size_t)(gj0 + 1) * n + gi0 + 8] = v3;
                }
            }
        }
}

// ---------------- host ----------------
extern "C" void kernel_launch(void* const* d_in, const int* in_sizes, int n_in,
                              void* d_out, int out_size) {
    const float* x     = (const float*)d_in[0];
    const int*   ei    = (const int*)d_in[1];      // int32! (JAX demotes int64)
    const float* ew    = (const float*)d_in[2];
    const float* W1    = (const float*)d_in[3];
    const float* b1    = (const float*)d_in[4];
    const float* W2    = (const float*)d_in[5];
    const float* b2    = (const float*)d_in[6];
    const float* Wih   = (const float*)d_in[7];
    const float* Whh   = (const float*)d_in[8];
    const float* bih   = (const float*)d_in[9];
    const float* bhh   = (const float*)d_in[10];
    const float* dbias = (const float*)d_in[11];
    float* out = (float*)d_out;

    int E = in_sizes[2];
    int N = in_sizes[0] / (T_STEPS * IN_DIM);
    if (N > NMAX) N = NMAX;                        // hard guard: never OOB scratch
    if (E > EDGEMAX - N) E = EDGEMAX - N;
    int M = T_STEPS * N;

    float  *p_WThh;
    __half *p_xh, *p_xaggh, *p_M2h, *p_zseqh;
    cudaGetSymbolAddress((void**)&p_xh,    g_xh);
    cudaGetSymbolAddress((void**)&p_xaggh, g_xaggh);
    cudaGetSymbolAddress((void**)&p_M2h,   g_M2h);
    cudaGetSymbolAddress((void**)&p_zseqh, g_zseqh);
    cudaGetSymbolAddress((void**)&p_WThh,  g_WThh);

    static int smem_set = 0;
    if (!smem_set) {
        cudaFuncSetAttribute(k_gru_all, cudaFuncAttributeMaxDynamicSharedMemorySize,
                             GRU_SMEM_FLOATS * (int)sizeof(float));
        cudaFuncSetAttribute(k_enc_mma, cudaFuncAttributeMaxDynamicSharedMemorySize,
                             ENC_SMEM_BYTES);
        smem_set = 1;
    }

    const int B = 256;
    // graph preprocessing
    k_init  <<<(N + B - 1) / B, B>>>(N);
    k_degcnt<<<(E + B - 1) / B, B>>>(ei, ew, E, N);
    k_dinv  <<<(N + B - 1) / B, B>>>(N);
    k_scan  <<<1, 1024>>>(N);
    k_fill  <<<(E + N + B - 1) / B, B>>>(ei, ew, E, N);

    // weights + input to fp16
    k_tohalf<<<(M * 32 + B - 1) / B, B>>>(x, p_xh, M * 32);
    k_convw <<<(28672 + B - 1) / B, B>>>(W1, W2, Wih);

    // encoder: AX (fp16) -> HMMA fused (relu(.W1+b1)).W2 -> fp16 -> A(.)+b2 (fp16)
    dim3 aggGrid((N * 32 + B - 1) / B, T_STEPS);
    k_agg_h  <<<aggGrid, B>>>((const __half2*)p_xh, (__half2*)p_xaggh, nullptr, N);
    k_enc_mma<<<(M + 127) / 128, B, ENC_SMEM_BYTES>>>(b1, p_M2h, M);
    k_agg_h  <<<aggGrid, B>>>((const __half2*)p_M2h, (__half2*)p_zseqh, b2, N);

    // GRU
    k_transpose<<<(EMB * G3 + B - 1) / B, B>>>(Whh, p_WThh);
    k_gi_mma<<<(M + 127) / 128, B>>>(bih, M);
    k_gru_all<<<(N + 63) / 64, B, GRU_SMEM_FLOATS * sizeof(float)>>>(bhh, out, N);

    // decoder (z already written by k_gru_all)
    int gb = (N + 127) / 128;
    k_decode_mma<<<dim3(gb, gb), B>>>(out, dbias, N);
}

// round 11
// speedup vs baseline: 2.7649x; 1.1243x over previous
#include <cuda_runtime.h>
#include <cuda_fp16.h>
#include <cstdint>

#define T_STEPS 12
#define IN_DIM  64
#define HID_DIM 128
#define EMB     64
#define G3      192

#define NMAX    10240
#define EDGEMAX 360448   /* > E + N */

// ---------------- scratch (static __device__, no allocations) ----------------
__device__ float  g_deg [NMAX];
__device__ float  g_dinv[NMAX];
__device__ int    g_cnt [NMAX];
__device__ int    g_off [NMAX + 1];
__device__ int    g_cur [NMAX];
__device__ int    g_alloc;
__device__ int2   g_ce  [EDGEMAX];                      // (row, norm-as-int)
__device__ __half g_xh  [(size_t)T_STEPS * NMAX * IN_DIM];
__device__ __half g_xaggh[(size_t)T_STEPS * NMAX * IN_DIM];
__device__ __half g_M2h [(size_t)T_STEPS * NMAX * EMB];
__device__ __half g_zseqh[(size_t)T_STEPS * NMAX * EMB];
__device__ __half g_gih [(size_t)T_STEPS * NMAX * G3];
__device__ __half g_hh  [(size_t)NMAX * EMB];
__device__ __half g_W1t [HID_DIM * IN_DIM];             // [n=128][k=64]
__device__ __half g_W2t [EMB * HID_DIM];                // [n=64][k=128]
__device__ __half g_Wihh[G3 * EMB];                     // [n=192][k=64] (= torch layout)
__device__ __half g_Whhh[G3 * EMB];                     // [n=192][k=64] (= torch layout)

// ---------------- small helpers ----------------
__device__ __forceinline__ float sigf(float x) { return 1.f / (1.f + __expf(-x)); }

__device__ __forceinline__ float softplusf(float x) {
    float u = __expf(-fabsf(x));                 // = exp(x) when x<0
    float r = fmaxf(x, 0.f) + __logf(1.f + u);
    if (x < -15.f) r = u;                        // avoid 1+u==1 rounding
    return r;
}

__device__ __forceinline__ void mma16816(float* d, unsigned a0, unsigned a1, unsigned a2, unsigned a3,
                                         unsigned b0, unsigned b1) {
    asm volatile("mma.sync.aligned.m16n8k16.row.col.f32.f16.f16.f32 "
        "{%0,%1,%2,%3}, {%4,%5,%6,%7}, {%8,%9}, {%0,%1,%2,%3};"
        : "+f"(d[0]), "+f"(d[1]), "+f"(d[2]), "+f"(d[3])
        : "r"(a0), "r"(a1), "r"(a2), "r"(a3), "r"(b0), "r"(b1));
}

// ---------------- graph preprocessing ----------------
__global__ void k_init(int n) {
    int i = blockIdx.x * blockDim.x + threadIdx.x;
    if (i == 0) g_alloc = 0;
    if (i < n) { g_deg[i] = 1.f; g_cnt[i] = 1; }   // self-loop weight/count
}

// edge_index is INT32 (JAX without x64 demotes int64 -> int32): layout [2, E]
__global__ void k_degcnt(const int* __restrict__ ei, const float* __restrict__ ew, int E, int n) {
    int e = blockIdx.x * blockDim.x + threadIdx.x;
    if (e < E) {
        int c = ei[E + e];
        c = min(max(c, 0), n - 1);               // defensive clamp
        atomicAdd(&g_deg[c], ew[e]);
        atomicAdd(&g_cnt[c], 1);
    }
}

// dinv + CSR segment allocation (order-free: bucket order is irrelevant)
__global__ void k_dinv(int n) {
    int i = blockIdx.x * blockDim.x + threadIdx.x;
    if (i < n) {
        float d = g_deg[i];
        g_dinv[i] = (d > 0.f) ? rsqrtf(d) : 0.f;
        int off = atomicAdd(&g_alloc, g_cnt[i]);
        g_off[i] = off;
        g_cur[i] = off;
    }
}

__global__ void k_fill(const int* __restrict__ ei, const float* __restrict__ ew, int E, int n) {
    int e = blockIdx.x * blockDim.x + threadIdx.x;
    int total = E + n;
    if (e >= total) return;
    int r, c; float w;
    if (e < E) {
        r = ei[e]; c = ei[E + e]; w = ew[e];
        r = min(max(r, 0), n - 1);
        c = min(max(c, 0), n - 1);
    }
    else       { r = c = e - E; w = 1.f; }
    float norm = g_dinv[r] * w * g_dinv[c];
    int pos = atomicAdd(&g_cur[c], 1);
    pos = min(max(pos, 0), EDGEMAX - 1);         // defensive clamp
    g_ce[pos] = make_int2(r, __float_as_int(norm));
}

// ---------------- combined fp16 prep: x and all weights ----------------
__global__ void k_prep(const float* __restrict__ x, const float* __restrict__ W1,
                       const float* __restrict__ W2, const float* __restrict__ Wih,
                       const float* __restrict__ Whh, int cnt2x) {
    int i = blockIdx.x * blockDim.x + threadIdx.x;
    if (i < cnt2x) {
        float2 v = ((const float2*)x)[i];
        ((__half2*)g_xh)[i] = __float22half2_rn(v);
        return;
    }
    int j = i - cnt2x;
    if (j < 8192) {                              // W1t[n][k] = W1[k][n], n<128,k<64
        int nn = j >> 6, k = j & 63;
        g_W1t[j] = __float2half_rn(W1[k * 128 + nn]);
    } else if (j < 16384) {                      // W2t[n][k] = W2[k][n], n<64,k<128
        int l = j - 8192;
        int nn = l >> 7, k = l & 127;
        g_W2t[l] = __float2half_rn(W2[k * 64 + nn]);
    } else if (j < 28672) {                      // Wih direct ([192][64] already [n][k])
        g_Wihh[j - 16384] = __float2half_rn(Wih[j - 16384]);
    } else if (j < 40960) {                      // Whh direct
        g_Whhh[j - 28672] = __float2half_rn(Whh[j - 28672]);
    }
}

// ---------------- aggregation (fp16 gather, fp32 accumulate, fp16 out), warp/node ----
__global__ void k_agg_h(const __half2* __restrict__ in, __half2* __restrict__ out,
                        const float* __restrict__ bias, int n) {
    int nd   = (blockIdx.x * blockDim.x + threadIdx.x) >> 5;
    int lane = threadIdx.x & 31;
    int t    = blockIdx.y;
    if (nd >= n) return;
    int s = g_off[nd], e = s + g_cnt[nd];
    const __half2* base = in + (size_t)t * n * 32;
    float a0 = 0.f, a1 = 0.f;
    int j = s;
    for (; j + 3 < e; j += 4) {                  // 4-way unroll for MLP
        int2 p0 = g_ce[j], p1 = g_ce[j + 1], p2 = g_ce[j + 2], p3 = g_ce[j + 3];
        float2 v0 = __half22float2(base[(size_t)p0.x * 32 + lane]);
        float2 v1 = __half22float2(base[(size_t)p1.x * 32 + lane]);
        float2 v2 = __half22float2(base[(size_t)p2.x * 32 + lane]);
        float2 v3 = __half22float2(base[(size_t)p3.x * 32 + lane]);
        float w0 = __int_as_float(p0.y), w1 = __int_as_float(p1.y);
        float w2 = __int_as_float(p2.y), w3 = __int_as_float(p3.y);
        a0 = fmaf(w0, v0.x, a0); a1 = fmaf(w0, v0.y, a1);
        a0 = fmaf(w1, v1.x, a0); a1 = fmaf(w1, v1.y, a1);
        a0 = fmaf(w2, v2.x, a0); a1 = fmaf(w2, v2.y, a1);
        a0 = fmaf(w3, v3.x, a0); a1 = fmaf(w3, v3.y, a1);
    }
    for (; j < e; j++) {
        int2 p0 = g_ce[j];
        float2 v0 = __half22float2(base[(size_t)p0.x * 32 + lane]);
        float w0 = __int_as_float(p0.y);
        a0 = fmaf(w0, v0.x, a0); a1 = fmaf(w0, v0.y, a1);
    }
    if (bias) { a0 += bias[lane * 2]; a1 += bias[lane * 2 + 1]; }
    out[((size_t)t * n + nd) * 32 + lane] = __floats2half2_rn(a0, a1);
}

// ---------------- fused encoder on HMMA: M2 = relu(xagg@W1+b1)@W2 (all fp16 ops) -------
#define ENC_SMEM_BYTES 71680
__global__ void __launch_bounds__(256) k_enc_mma(const float* __restrict__ b1,
                                                 __half* __restrict__ M2h, int M) {
    extern __shared__ __align__(16) unsigned char ES[];
    unsigned char* Ax  = ES;
    unsigned char* W2t = ES;
    unsigned char* W1t = ES + 18432;
    unsigned char* Hs  = ES + 36864;
    int r0 = blockIdx.x * 128;
    int tid = threadIdx.x;
    for (int idx = tid; idx < 1024; idx += 256) {
        int r = idx >> 3, c = idx & 7;
        uint4 v = make_uint4(0u, 0u, 0u, 0u);
        if (r0 + r < M) v = *(const uint4*)(g_xaggh + (size_t)(r0 + r) * 64 + c * 8);
        *(uint4*)(Ax + r * 144 + c * 16) = v;
        *(uint4*)(W1t + r * 144 + c * 16) = *(const uint4*)(g_W1t + r * 64 + c * 8);
    }
    __syncthreads();
    int wid = tid >> 5, lane = tid & 31, lr = lane >> 2, lm = lane & 3;
    int mb = wid << 4;
    float d1[16][4];
    #pragma unroll
    for (int ni = 0; ni < 16; ni++)
        #pragma unroll
        for (int q = 0; q < 4; q++) d1[ni][q] = 0.f;
    #pragma unroll
    for (int ks = 0; ks < 4; ks++) {
        int ra = mb + lr;
        unsigned a0 = *(const unsigned*)(Ax + ra * 144       + ks * 32      + lm * 4);
        unsigned a1 = *(const unsigned*)(Ax + (ra + 8) * 144 + ks * 32      + lm * 4);
        unsigned a2 = *(const unsigned*)(Ax + ra * 144       + ks * 32 + 16 + lm * 4);
        unsigned a3 = *(const unsigned*)(Ax + (ra + 8) * 144 + ks * 32 + 16 + lm * 4);
        #pragma unroll
        for (int ni = 0; ni < 16; ni++) {
            int rb = ni * 8 + lr;
            unsigned b0 = *(const unsigned*)(W1t + rb * 144 + ks * 32      + lm * 4);
            unsigned b1v = *(const unsigned*)(W1t + rb * 144 + ks * 32 + 16 + lm * 4);
            mma16816(d1[ni], a0, a1, a2, a3, b0, b1v);
        }
    }
    __syncthreads();                             // Ax reads done -> buffer reusable
    #pragma unroll
    for (int ni = 0; ni < 16; ni++) {            // relu+bias -> Hs (fp16)
        int col = ni * 8 + lm * 2;
        float bb0 = b1[col], bb1 = b1[col + 1];
        __half2 h01 = __floats2half2_rn(fmaxf(d1[ni][0] + bb0, 0.f), fmaxf(d1[ni][1] + bb1, 0.f));
        __half2 h23 = __floats2half2_rn(fmaxf(d1[ni][2] + bb0, 0.f), fmaxf(d1[ni][3] + bb1, 0.f));
        *(unsigned*)(Hs + (mb + lr) * 272     + col * 2) = *(unsigned*)&h01;
        *(unsigned*)(Hs + (mb + lr + 8) * 272 + col * 2) = *(unsigned*)&h23;
    }
    for (int idx = tid; idx < 1024; idx += 256) { // W2t: 64 rows x 16 chunks
        int r = idx >> 4, c = idx & 15;
        *(uint4*)(W2t + r * 272 + c * 16) = *(const uint4*)(g_W2t + r * 128 + c * 8);
    }
    __syncthreads();
    float d2[8][4];
    #pragma unroll
    for (int ni = 0; ni < 8; ni++)
        #pragma unroll
        for (int q = 0; q < 4; q++) d2[ni][q] = 0.f;
    #pragma unroll
    for (int ks = 0; ks < 8; ks++) {
        int ra = mb + lr;
        unsigned a0 = *(const unsigned*)(Hs + ra * 272       + ks * 32      + lm * 4);
        unsigned a1 = *(const unsigned*)(Hs + (ra + 8) * 272 + ks * 32      + lm * 4);
        unsigned a2 = *(const unsigned*)(Hs + ra * 272       + ks * 32 + 16 + lm * 4);
        unsigned a3 = *(const unsigned*)(Hs + (ra + 8) * 272 + ks * 32 + 16 + lm * 4);
        #pragma unroll
        for (int ni = 0; ni < 8; ni++) {
            int rb = ni * 8 + lr;
            unsigned b0 = *(const unsigned*)(W2t + rb * 272 + ks * 32      + lm * 4);
            unsigned b1v = *(const unsigned*)(W2t + rb * 272 + ks * 32 + 16 + lm * 4);
            mma16816(d2[ni], a0, a1, a2, a3, b0, b1v);
        }
    }
    #pragma unroll
    for (int ni = 0; ni < 8; ni++) {
        int col = ni * 8 + lm * 2;
        int row = r0 + mb + lr;
        if (row < M) {
            __half2 h = __floats2half2_rn(d2[ni][0], d2[ni][1]);
            *(unsigned*)(M2h + (size_t)row * 64 + col) = *(unsigned*)&h;
        }
        if (row + 8 < M) {
            __half2 h = __floats2half2_rn(d2[ni][2], d2[ni][3]);
            *(unsigned*)(M2h + (size_t)(row + 8) * 64 + col) = *(unsigned*)&h;
        }
    }
}

// ---------------- gi GEMM on HMMA: gi = zseq @ Wih^T + (bih [+bhh r,z]) (fp16 out) -----
__global__ void __launch_bounds__(256) k_gi_mma(const float* __restrict__ bih,
                                                const float* __restrict__ bhh, int M) {
    __shared__ __align__(16) unsigned char Az[128 * 144];
    __shared__ __align__(16) unsigned char Wm[192 * 144];
    int r0 = blockIdx.x * 128;
    int tid = threadIdx.x;
    for (int idx = tid; idx < 1024; idx += 256) {
        int r = idx >> 3, c = idx & 7;
        uint4 v = make_uint4(0u, 0u, 0u, 0u);
        if (r0 + r < M) v = *(const uint4*)(g_zseqh + (size_t)(r0 + r) * 64 + c * 8);
        *(uint4*)(Az + r * 144 + c * 16) = v;
    }
    for (int idx = tid; idx < 1536; idx += 256) {
        int r = idx >> 3, c = idx & 7;
        *(uint4*)(Wm + r * 144 + c * 16) = *(const uint4*)(g_Wihh + r * 64 + c * 8);
    }
    __syncthreads();
    int wid = tid >> 5, lane = tid & 31, lr = lane >> 2, lm = lane & 3;
    int mb = wid << 4;
    float d[24][4];
    #pragma unroll
    for (int ni = 0; ni < 24; ni++)
        #pragma unroll
        for (int q = 0; q < 4; q++) d[ni][q] = 0.f;
    #pragma unroll
    for (int ks = 0; ks < 4; ks++) {
        int ra = mb + lr;
        unsigned a0 = *(const unsigned*)(Az + ra * 144       + ks * 32      + lm * 4);
        unsigned a1 = *(const unsigned*)(Az + (ra + 8) * 144 + ks * 32      + lm * 4);
        unsigned a2 = *(const unsigned*)(Az + ra * 144       + ks * 32 + 16 + lm * 4);
        unsigned a3 = *(const unsigned*)(Az + (ra + 8) * 144 + ks * 32 + 16 + lm * 4);
        #pragma unroll
        for (int ni = 0; ni < 24; ni++) {
            int rb = ni * 8 + lr;
            unsigned b0 = *(const unsigned*)(Wm + rb * 144 + ks * 32      + lm * 4);
            unsigned b1v = *(const unsigned*)(Wm + rb * 144 + ks * 32 + 16 + lm * 4);
            mma16816(d[ni], a0, a1, a2, a3, b0, b1v);
        }
    }
    #pragma unroll
    for (int ni = 0; ni < 24; ni++) {
        int col = ni * 8 + lm * 2;
        float bb0 = bih[col], bb1 = bih[col + 1];
        if (ni < 16) { bb0 += bhh[col]; bb1 += bhh[col + 1]; }  // fold bhh_r, bhh_z
        int row = r0 + mb + lr;
        if (row < M) {
            __half2 h = __floats2half2_rn(d[ni][0] + bb0, d[ni][1] + bb1);
            *(unsigned*)(g_gih + (size_t)row * 192 + col) = *(unsigned*)&h;
        }
        if (row + 8 < M) {
            __half2 h = __floats2half2_rn(d[ni][2] + bb0, d[ni][3] + bb1);
            *(unsigned*)(g_gih + (size_t)(row + 8) * 192 + col) = *(unsigned*)&h;
        }
    }
}

// ---------------- GRU on HMMA: all 12 steps, fp32 h master in registers -------------
// Block: 128 threads (4 warps), 64 rows. gh = fp16(h) @ Whh^T on tensor cores.
__global__ void __launch_bounds__(128) k_gru_mma(const float* __restrict__ bhh,
                                                 float* __restrict__ out, int n) {
    __shared__ __align__(16) unsigned char Wm[192 * 144];
    __shared__ __align__(16) unsigned char Ht[64 * 144];
    int r0 = blockIdx.x * 64;
    int tid = threadIdx.x;
    for (int idx = tid; idx < 1536; idx += 128) {
        int r = idx >> 3, c = idx & 7;
        *(uint4*)(Wm + r * 144 + c * 16) = *(const uint4*)(g_Whhh + r * 64 + c * 8);
    }
    for (int idx = tid; idx < 576; idx += 128)   // zero Ht (64*144 B = 576 uint4)
        ((uint4*)Ht)[idx] = make_uint4(0u, 0u, 0u, 0u);

    int wid = tid >> 5, lane = tid & 31, lr = lane >> 2, lm = lane & 3;
    int mb = wid << 4;
    int row_a = mb + lr;
    int grow0 = r0 + row_a, grow1 = grow0 + 8;
    bool v0 = grow0 < n, v1 = grow1 < n;

    float bn0[8], bn1[8];
    float hreg[8][4];
    #pragma unroll
    for (int ni = 0; ni < 8; ni++) {
        int f0 = ni * 8 + lm * 2;
        float2 b = *(const float2*)(bhh + 128 + f0);
        bn0[ni] = b.x; bn1[ni] = b.y;
        hreg[ni][0] = hreg[ni][1] = hreg[ni][2] = hreg[ni][3] = 0.f;
    }
    __syncthreads();

    for (int t = 0; t < T_STEPS; t++) {
        float d[24][4];
        #pragma unroll
        for (int ni = 0; ni < 24; ni++)
            #pragma unroll
            for (int q = 0; q < 4; q++) d[ni][q] = 0.f;
        #pragma unroll
        for (int ks = 0; ks < 4; ks++) {
            unsigned a0 = *(const unsigned*)(Ht + row_a * 144       + ks * 32      + lm * 4);
            unsigned a1 = *(const unsigned*)(Ht + (row_a + 8) * 144 + ks * 32      + lm * 4);
            unsigned a2 = *(const unsigned*)(Ht + row_a * 144       + ks * 32 + 16 + lm * 4);
            unsigned a3 = *(const unsigned*)(Ht + (row_a + 8) * 144 + ks * 32 + 16 + lm * 4);
            #pragma unroll
            for (int ni = 0; ni < 24; ni++) {
                int rb = ni * 8 + lr;
                unsigned b0 = *(const unsigned*)(Wm + rb * 144 + ks * 32      + lm * 4);
                unsigned b1v = *(const unsigned*)(Wm + rb * 144 + ks * 32 + 16 + lm * 4);
                mma16816(d[ni], a0, a1, a2, a3, b0, b1v);
            }
        }
        __syncthreads();                         // Ht reads complete before overwrite
        const __half2* gp0 = (const __half2*)(g_gih + ((size_t)t * n + grow0) * 192);
        const __half2* gp1 = (const __half2*)(g_gih + ((size_t)t * n + grow1) * 192);
        #pragma unroll
        for (int ni = 0; ni < 8; ni++) {
            int hi = ni * 4 + lm;
            int f0 = ni * 8 + lm * 2;
            if (v0) {
                float2 gr = __half22float2(gp0[hi]);
                float2 gz = __half22float2(gp0[32 + hi]);
                float2 gn = __half22float2(gp0[64 + hi]);
                float rr0 = sigf(gr.x + d[ni][0]);
                float rr1 = sigf(gr.y + d[ni][1]);
                float zz0 = sigf(gz.x + d[ni + 8][0]);
                float zz1 = sigf(gz.y + d[ni + 8][1]);
                float ng0 = tanhf(gn.x + rr0 * (d[ni + 16][0] + bn0[ni]));
                float ng1 = tanhf(gn.y + rr1 * (d[ni + 16][1] + bn1[ni]));
                hreg[ni][0] = (1.f - zz0) * ng0 + zz0 * hreg[ni][0];
                hreg[ni][1] = (1.f - zz1) * ng1 + zz1 * hreg[ni][1];
                __half2 h = __floats2half2_rn(hreg[ni][0], hreg[ni][1]);
                *(unsigned*)(Ht + row_a * 144 + f0 * 2) = *(unsigned*)&h;
            }
            if (v1) {
                float2 gr = __half22float2(gp1[hi]);
                float2 gz = __half22float2(gp1[32 + hi]);
                float2 gn = __half22float2(gp1[64 + hi]);
                float rr0 = sigf(gr.x + d[ni][2]);
                float rr1 = sigf(gr.y + d[ni][3]);
                float zz0 = sigf(gz.x + d[ni + 8][2]);
                float zz1 = sigf(gz.y + d[ni + 8][3]);
                float ng0 = tanhf(gn.x + rr0 * (d[ni + 16][2] + bn0[ni]));
                float ng1 = tanhf(gn.y + rr1 * (d[ni + 16][3] + bn1[ni]));
                hreg[ni][2] = (1.f - zz0) * ng0 + zz0 * hreg[ni][2];
                hreg[ni][3] = (1.f - zz1) * ng1 + zz1 * hreg[ni][3];
                __half2 h = __floats2half2_rn(hreg[ni][2], hreg[ni][3]);
                *(unsigned*)(Ht + (row_a + 8) * 144 + f0 * 2) = *(unsigned*)&h;
            }
        }
        __syncthreads();                         // updates visible before next step
    }
    // writeback: z (fp32 at out + n*n) and fp16 copy for decoder
    #pragma unroll
    for (int ni = 0; ni < 8; ni++) {
        int f0 = ni * 8 + lm * 2;
        if (v0) {
            *(float2*)(out + (size_t)n * n + (size_t)grow0 * 64 + f0) =
                make_float2(hreg[ni][0], hreg[ni][1]);
            __half2 h = __floats2half2_rn(hreg[ni][0], hreg[ni][1]);
            *(unsigned*)(g_hh + (size_t)grow0 * 64 + f0) = *(unsigned*)&h;
        }
        if (v1) {
            *(float2*)(out + (size_t)n * n + (size_t)grow1 * 64 + f0) =
                make_float2(hreg[ni][2], hreg[ni][3]);
            __half2 h = __floats2half2_rn(hreg[ni][2], hreg[ni][3]);
            *(unsigned*)(g_hh + (size_t)grow1 * 64 + f0) = *(unsigned*)&h;
        }
    }
}

// ---------------- decoder: softplus(z @ z^T + b), symmetric, HMMA fp16 ----------------
// smem tile: 128 rows x 64 halves, row stride 144 B, 16B-chunk swizzle c' = c ^ (2*(r&3))
__device__ __forceinline__ unsigned sw_ad(int r, int c) {
    return (unsigned)(r * 144 + (((c ^ ((r & 3) << 1)) & 7) << 4));
}

__global__ void __launch_bounds__(256) k_decode_mma(float* __restrict__ C,
                                                    const float* __restrict__ dbias, int n) {
    int bj = blockIdx.x, bi = blockIdx.y;
    if (bj < bi) return;
    __shared__ __align__(16) unsigned char Asm[128 * 144];
    __shared__ __align__(16) unsigned char Bsm[128 * 144];
    int tid = threadIdx.x;
    int i0 = bi * 128, j0 = bj * 128;
    for (int idx = tid; idx < 1024; idx += 256) {
        int r = idx >> 3, c = idx & 7;
        uint4 va = make_uint4(0u, 0u, 0u, 0u), vb = va;
        if (i0 + r < n) va = *(const uint4*)(g_hh + (size_t)(i0 + r) * 64 + c * 8);
        if (j0 + r < n) vb = *(const uint4*)(g_hh + (size_t)(j0 + r) * 64 + c * 8);
        *(uint4*)(Asm + sw_ad(r, c)) = va;
        *(uint4*)(Bsm + sw_ad(r, c)) = vb;
    }
    __syncthreads();
    int wid = tid >> 5, lane = tid & 31;
    int lr = lane >> 2, lm = lane & 3;
    int R  = (wid >> 1) << 5;                    // warp m base (0,32,64,96)
    int Jb = (wid & 1) << 6;                     // warp n base (0,64)
    float d[2][8][4];
    #pragma unroll
    for (int mi = 0; mi < 2; mi++)
        #pragma unroll
        for (int ni = 0; ni < 8; ni++)
            #pragma unroll
            for (int q = 0; q < 4; q++) d[mi][ni][q] = 0.f;

    #pragma unroll
    for (int ks = 0; ks < 4; ks++) {
        unsigned a[2][4];
        #pragma unroll
        for (int mi = 0; mi < 2; mi++) {
            int r_ = R + (mi << 4) + lr;
            a[mi][0] = *(const unsigned*)(Asm + sw_ad(r_,     2 * ks)     + (lm << 2));
            a[mi][1] = *(const unsigned*)(Asm + sw_ad(r_ + 8, 2 * ks)     + (lm << 2));
            a[mi][2] = *(const unsigned*)(Asm + sw_ad(r_,     2 * ks + 1) + (lm << 2));
            a[mi][3] = *(const unsigned*)(Asm + sw_ad(r_ + 8, 2 * ks + 1) + (lm << 2));
        }
        #pragma unroll
        for (int ni = 0; ni < 8; ni++) {
            int jr = Jb + (ni << 3) + lr;
            unsigned b0 = *(const unsigned*)(Bsm + sw_ad(jr, 2 * ks)     + (lm << 2));
            unsigned b1 = *(const unsigned*)(Bsm + sw_ad(jr, 2 * ks + 1) + (lm << 2));
            #pragma unroll
            for (int mi = 0; mi < 2; mi++) {
                asm volatile("mma.sync.aligned.m16n8k16.row.col.f32.f16.f16.f32 "
                    "{%0,%1,%2,%3}, {%4,%5,%6,%7}, {%8,%9}, {%0,%1,%2,%3};"
                    : "+f"(d[mi][ni][0]), "+f"(d[mi][ni][1]),
                      "+f"(d[mi][ni][2]), "+f"(d[mi][ni][3])
                    : "r"(a[mi][0]), "r"(a[mi][1]), "r"(a[mi][2]), "r"(a[mi][3]),
                      "r"(b0), "r"(b1));
            }
        }
    }
    float db = dbias[0];
    #pragma unroll
    for (int mi = 0; mi < 2; mi++)
        #pragma unroll
        for (int ni = 0; ni < 8; ni++) {
            int gi0 = i0 + R + (mi << 4) + lr;
            int gj0 = j0 + Jb + (ni << 3) + (lm << 1);
            float v0 = softplusf(d[mi][ni][0] + db);
            float v1 = softplusf(d[mi][ni][1] + db);
            float v2 = softplusf(d[mi][ni][2] + db);
            float v3 = softplusf(d[mi][ni][3] + db);
            if (gi0 < n) {
                if (gj0 + 1 < n)      *(float2*)(C + (size_t)gi0 * n + gj0) = make_float2(v0, v1);
                else if (gj0 < n)     C[(size_t)gi0 * n + gj0] = v0;
            }
            if (gi0 + 8 < n) {
                if (gj0 + 1 < n)      *(float2*)(C + (size_t)(gi0 + 8) * n + gj0) = make_float2(v2, v3);
                else if (gj0 < n)     C[(size_t)(gi0 + 8) * n + gj0] = v2;
            }
            if (bi != bj) {          // mirror C[j][i] = C[i][j]
                if (gj0 < n) {
                    if (gi0 < n)     C[(size_t)gj0 * n + gi0]     = v0;
                    if (gi0 + 8 < n) C[(size_t)gj0 * n + gi0 + 8] = v2;
                }
                if (gj0 + 1 < n) {
                    if (gi0 < n)     C[(size_t)(gj0 + 1) * n + gi0]     = v1;
                    if (gi0 + 8 < n) C[(size_t)(gj0 + 1) * n + gi0 + 8] = v3;
                }
            }
        }
}

// ---------------- host ----------------
extern "C" void kernel_launch(void* const* d_in, const int* in_sizes, int n_in,
                              void* d_out, int out_size) {
    const float* x     = (const float*)d_in[0];
    const int*   ei    = (const int*)d_in[1];      // int32! (JAX demotes int64)
    const float* ew    = (const float*)d_in[2];
    const float* W1    = (const float*)d_in[3];
    const float* b1    = (const float*)d_in[4];
    const float* W2    = (const float*)d_in[5];
    const float* b2    = (const float*)d_in[6];
    const float* Wih   = (const float*)d_in[7];
    const float* Whh   = (const float*)d_in[8];
    const float* bih   = (const float*)d_in[9];
    const float* bhh   = (const float*)d_in[10];
    const float* dbias = (const float*)d_in[11];
    float* out = (float*)d_out;

    int E = in_sizes[2];
    int N = in_sizes[0] / (T_STEPS * IN_DIM);
    if (N > NMAX) N = NMAX;                        // hard guard: never OOB scratch
    if (E > EDGEMAX - N) E = EDGEMAX - N;
    int M = T_STEPS * N;

    __half *p_xh, *p_xaggh, *p_M2h, *p_zseqh;
    cudaGetSymbolAddress((void**)&p_xh,    g_xh);
    cudaGetSymbolAddress((void**)&p_xaggh, g_xaggh);
    cudaGetSymbolAddress((void**)&p_M2h,   g_M2h);
    cudaGetSymbolAddress((void**)&p_zseqh, g_zseqh);

    static int smem_set = 0;
    if (!smem_set) {
        cudaFuncSetAttribute(k_enc_mma, cudaFuncAttributeMaxDynamicSharedMemorySize,
                             ENC_SMEM_BYTES);
        smem_set = 1;
    }

    const int B = 256;
    // graph preprocessing (no scan: segment offsets via atomic allocation)
    k_init  <<<(N + B - 1) / B, B>>>(N);
    k_degcnt<<<(E + B - 1) / B, B>>>(ei, ew, E, N);
    k_dinv  <<<(N + B - 1) / B, B>>>(N);
    k_fill  <<<(E + N + B - 1) / B, B>>>(ei, ew, E, N);

    // fp16 prep (x + all weights, one launch)
    k_prep<<<(M * 32 + 40960 + B - 1) / B, B>>>(x, W1, W2, Wih, Whh, M * 32);

    // encoder: AX (fp16) -> HMMA fused (relu(.W1+b1)).W2 -> fp16 -> A(.)+b2 (fp16)
    dim3 aggGrid((N * 32 + B - 1) / B, T_STEPS);
    k_agg_h  <<<aggGrid, B>>>((const __half2*)p_xh, (__half2*)p_xaggh, nullptr, N);
    k_enc_mma<<<(M + 127) / 128, B, ENC_SMEM_BYTES>>>(b1, p_M2h, M);
    k_agg_h  <<<aggGrid, B>>>((const __half2*)p_M2h, (__half2*)p_zseqh, b2, N);

    // GRU (gi with bhh_r/bhh_z folded; all 12 steps on HMMA)
    k_gi_mma<<<(M + 127) / 128, B>>>(bih, bhh, M);
    k_gru_mma<<<(N + 63) / 64, 128>>>(bhh, out, N);

    // decoder (z already written by k_gru_mma)
    int gb = (N + 127) / 128;
    k_decode_mma<<<dim3(gb, gb), B>>>(out, dbias, N);
}